// round 9
// baseline (speedup 1.0000x reference)
#include <cuda_runtime.h>
#include <cuda_bf16.h>
#include <math.h>
#include <stdint.h>

#define TT 2048      // B*S tokens
#define DD 1024      // model dim
#define FFD 4096     // ff dim
#define VV 32000     // vocab
#define HH 16        // heads
#define HD 64        // head dim
#define LL 6         // layers
#define SS 1024      // seq len
#define BB 2         // batch

// ---------------- scratch (no allocation allowed) ----------------
__device__ float g_x[TT * DD];
__device__ float g_h[TT * DD];
__device__ float g_q[TT * DD];
__device__ float g_k[TT * DD];
__device__ float g_v[TT * DD];
__device__ float g_at[TT * DD];
__device__ float g_ff[TT * FFD];

// ---------------- embedding + sinusoidal positional encoding ----------------
__global__ void embed_kernel(const float* __restrict__ emb,
                             const int* __restrict__ ids,
                             float* __restrict__ x) {
    int idx = blockIdx.x * 256 + threadIdx.x;
    if (idx >= TT * DD) return;
    int t = idx >> 10;
    int d = idx & (DD - 1);
    int pos = t & (SS - 1);
    float val = emb[ids[t] * DD + d] * 32.0f;
    float ang = (float)pos * expf((float)(d & ~1) * (-9.210340371976184f / 1024.0f));
    val += (d & 1) ? cosf(ang) : sinf(ang);
    x[idx] = val;
}

// ---------------- layernorm ----------------
__global__ __launch_bounds__(256) void ln_kernel(const float* __restrict__ x,
                                                 const float* __restrict__ g,
                                                 const float* __restrict__ bta,
                                                 float* __restrict__ out) {
    int row = blockIdx.x;
    const float* xr = x + (size_t)row * DD;
    float s1 = 0.f, s2 = 0.f;
    for (int i = threadIdx.x; i < DD; i += 256) {
        float v = xr[i];
        s1 += v;
        s2 = fmaf(v, v, s2);
    }
    for (int o = 16; o; o >>= 1) {
        s1 += __shfl_xor_sync(0xffffffffu, s1, o);
        s2 += __shfl_xor_sync(0xffffffffu, s2, o);
    }
    __shared__ float r1[8], r2[8];
    __shared__ float smean, srstd;
    int w = threadIdx.x >> 5, lane = threadIdx.x & 31;
    if (lane == 0) { r1[w] = s1; r2[w] = s2; }
    __syncthreads();
    if (threadIdx.x == 0) {
        float t1 = 0.f, t2 = 0.f;
        for (int i = 0; i < 8; i++) { t1 += r1[i]; t2 += r2[i]; }
        float mean = t1 * (1.0f / DD);
        float var  = t2 * (1.0f / DD) - mean * mean;
        smean = mean;
        srstd = rsqrtf(var + 1e-5f);
    }
    __syncthreads();
    float mean = smean, rstd = srstd;
    for (int i = threadIdx.x; i < DD; i += 256)
        out[(size_t)row * DD + i] = (xr[i] - mean) * rstd * g[i] + bta[i];
}

// ---------------- tf32 helpers ----------------
__device__ __forceinline__ float2 split_tf32_f2(float f) {
    uint32_t hi;
    asm("cvt.rna.tf32.f32 %0, %1;" : "=r"(hi) : "f"(f));
    float h = __uint_as_float(hi);
    float r = f - h;
    uint32_t lo;
    asm("cvt.rna.tf32.f32 %0, %1;" : "=r"(lo) : "f"(r));
    float2 o;
    o.x = h;
    o.y = __uint_as_float(lo);
    return o;
}

__device__ __forceinline__ void mma_tf32(float* c, const uint32_t* a, const uint32_t* b) {
    asm volatile(
        "mma.sync.aligned.m16n8k8.row.col.f32.tf32.tf32.f32 "
        "{%0,%1,%2,%3}, {%4,%5,%6,%7}, {%8,%9}, {%0,%1,%2,%3};\n"
        : "+f"(c[0]), "+f"(c[1]), "+f"(c[2]), "+f"(c[3])
        : "r"(a[0]), "r"(a[1]), "r"(a[2]), "r"(a[3]), "r"(b[0]), "r"(b[1]));
}

// ---------------- 3xTF32 tensor-core GEMM: 128x128x32 tiles ----------------
// smem holds PRE-SPLIT (hi,lo) pairs as float2; SINGLE buffer (67.5KB -> 2 CTAs/SM).
// C[M,N] = A[M,K] @ B[K,N] (+bias)(gelu?)(+res). M%128==0, N%128==0, K%32==0.
#define S2 132                       // float2 row stride
#define GEMM_SMEM (2 * 32 * S2 * 8)  // bytes = 67584 (A + B, one buffer)

__device__ __forceinline__ void gemm_body_tc(const float* __restrict__ A,
                                             const float* __restrict__ Bw,
                                             const float* __restrict__ bias,
                                             const float* __restrict__ res,
                                             float* __restrict__ C,
                                             int M, int N, int K, int gelu) {
    extern __shared__ float2 sm2[];
    float2* Ah = sm2;                 // [32][S2]  (k-major, pre-split A)
    float2* Bh = sm2 + 32 * S2;       // [32][S2]  (k-major, pre-split B)
    int t = threadIdx.x;
    int bm = blockIdx.y, bn = blockIdx.x;
    int w = t >> 5, lane = t & 31;
    int wm = w >> 2, wn = w & 3;                 // warps: 2(m) x 4(n)
    int m_base = wm * 64, n_base = wn * 32;
    int gid = lane >> 2, tig = lane & 3;

    // loader maps
    int am = t & 127;                 // A: m (fixed), k4 base = t>>7
    int ak4 = t >> 7;
    const float* Arow = A + (size_t)(bm * 128 + am) * K;
    int bn4 = t & 31;                 // B: 4 consecutive n
    int bkr = t >> 5;                 // k row base (+8 per i)
    const float* Bcol = Bw + bn * 128 + bn4 * 4;

    float acc[4][4][4];
#pragma unroll
    for (int mf = 0; mf < 4; mf++)
#pragma unroll
        for (int nf = 0; nf < 4; nf++)
#pragma unroll
            for (int r = 0; r < 4; r++) acc[mf][nf][r] = 0.f;

    int ntiles = K >> 5;
    float4 ra[4], rb[4];

    // ---- prefetch tile 0 into regs, split+store ----
#pragma unroll
    for (int i = 0; i < 4; i++) {
        ra[i] = *(const float4*)(Arow + (ak4 + 2 * i) * 4);
        rb[i] = *(const float4*)(Bcol + (size_t)(bkr + 8 * i) * N);
    }
#pragma unroll
    for (int i = 0; i < 4; i++) {
        int k4 = ak4 + 2 * i;
        Ah[(k4 * 4 + 0) * S2 + am] = split_tf32_f2(ra[i].x);
        Ah[(k4 * 4 + 1) * S2 + am] = split_tf32_f2(ra[i].y);
        Ah[(k4 * 4 + 2) * S2 + am] = split_tf32_f2(ra[i].z);
        Ah[(k4 * 4 + 3) * S2 + am] = split_tf32_f2(ra[i].w);
        int kr = bkr + 8 * i;
        Bh[kr * S2 + bn4 * 4 + 0] = split_tf32_f2(rb[i].x);
        Bh[kr * S2 + bn4 * 4 + 1] = split_tf32_f2(rb[i].y);
        Bh[kr * S2 + bn4 * 4 + 2] = split_tf32_f2(rb[i].z);
        Bh[kr * S2 + bn4 * 4 + 3] = split_tf32_f2(rb[i].w);
    }
    __syncthreads();

    for (int tt = 0; tt < ntiles; tt++) {
        bool more = (tt + 1) < ntiles;
        if (more) {
            int k0 = (tt + 1) << 5;
#pragma unroll
            for (int i = 0; i < 4; i++) {
                ra[i] = *(const float4*)(Arow + k0 + (ak4 + 2 * i) * 4);
                rb[i] = *(const float4*)(Bcol + (size_t)(k0 + bkr + 8 * i) * N);
            }
        }

        // ---- compute on smem (pure LDS.64 + MMA) ----
#pragma unroll
        for (int ks = 0; ks < 32; ks += 8) {
            uint32_t bhi[4][2], blo[4][2];
#pragma unroll
            for (int nf = 0; nf < 4; nf++) {
                int nn = n_base + nf * 8 + gid;
                float2 x0 = Bh[(ks + tig) * S2 + nn];
                float2 x1 = Bh[(ks + tig + 4) * S2 + nn];
                bhi[nf][0] = __float_as_uint(x0.x);
                blo[nf][0] = __float_as_uint(x0.y);
                bhi[nf][1] = __float_as_uint(x1.x);
                blo[nf][1] = __float_as_uint(x1.y);
            }
#pragma unroll
            for (int mf = 0; mf < 4; mf++) {
                int mc = m_base + mf * 16 + gid;
                float2 a0 = Ah[(ks + tig) * S2 + mc];
                float2 a1 = Ah[(ks + tig) * S2 + mc + 8];
                float2 a2 = Ah[(ks + tig + 4) * S2 + mc];
                float2 a3 = Ah[(ks + tig + 4) * S2 + mc + 8];
                uint32_t ahi[4] = {__float_as_uint(a0.x), __float_as_uint(a1.x),
                                   __float_as_uint(a2.x), __float_as_uint(a3.x)};
                uint32_t alo[4] = {__float_as_uint(a0.y), __float_as_uint(a1.y),
                                   __float_as_uint(a2.y), __float_as_uint(a3.y)};
#pragma unroll
                for (int nf = 0; nf < 4; nf++) mma_tf32(acc[mf][nf], ahi, bhi[nf]);
#pragma unroll
                for (int nf = 0; nf < 4; nf++) mma_tf32(acc[mf][nf], ahi, blo[nf]);
#pragma unroll
                for (int nf = 0; nf < 4; nf++) mma_tf32(acc[mf][nf], alo, bhi[nf]);
            }
        }
        __syncthreads();

        // ---- split+store next tile ----
        if (more) {
#pragma unroll
            for (int i = 0; i < 4; i++) {
                int k4 = ak4 + 2 * i;
                Ah[(k4 * 4 + 0) * S2 + am] = split_tf32_f2(ra[i].x);
                Ah[(k4 * 4 + 1) * S2 + am] = split_tf32_f2(ra[i].y);
                Ah[(k4 * 4 + 2) * S2 + am] = split_tf32_f2(ra[i].z);
                Ah[(k4 * 4 + 3) * S2 + am] = split_tf32_f2(ra[i].w);
                int kr = bkr + 8 * i;
                Bh[kr * S2 + bn4 * 4 + 0] = split_tf32_f2(rb[i].x);
                Bh[kr * S2 + bn4 * 4 + 1] = split_tf32_f2(rb[i].y);
                Bh[kr * S2 + bn4 * 4 + 2] = split_tf32_f2(rb[i].z);
                Bh[kr * S2 + bn4 * 4 + 3] = split_tf32_f2(rb[i].w);
            }
            __syncthreads();
        }
    }

    // ---- epilogue: paired float2 stores ----
#pragma unroll
    for (int mf = 0; mf < 4; mf++) {
        int row0 = bm * 128 + m_base + mf * 16 + gid;
#pragma unroll
        for (int nf = 0; nf < 4; nf++) {
            int col = bn * 128 + n_base + nf * 8 + tig * 2;
            float bx = 0.f, by = 0.f;
            if (bias) { bx = bias[col]; by = bias[col + 1]; }
#pragma unroll
            for (int half = 0; half < 2; half++) {
                int row = row0 + half * 8;
                float vx = acc[mf][nf][half * 2 + 0] + bx;
                float vy = acc[mf][nf][half * 2 + 1] + by;
                if (gelu) {
                    vx = 0.5f * vx * (1.0f + erff(vx * 0.70710678118654752f));
                    vy = 0.5f * vy * (1.0f + erff(vy * 0.70710678118654752f));
                }
                size_t o = (size_t)row * N + col;
                if (res) {
                    float2 rr = *(const float2*)(res + o);
                    vx += rr.x; vy += rr.y;
                }
                float2 ov; ov.x = vx; ov.y = vy;
                *(float2*)(C + o) = ov;
            }
        }
    }
}

__global__ __launch_bounds__(256, 2) void sgemm_kernel(const float* A, const float* Bw,
                                                       const float* bias, const float* res,
                                                       float* C, int M, int N, int K, int gelu) {
    gemm_body_tc(A, Bw, bias, res, C, M, N, K, gelu);
}

__global__ __launch_bounds__(256, 2) void sgemm_qkv_kernel(const float* A,
                                                           const float* Wq, const float* Wk, const float* Wv,
                                                           const float* bq, const float* bk, const float* bv,
                                                           float* Q, float* Ko, float* Vo) {
    const float* W; const float* bi; float* C;
    if (blockIdx.z == 0)      { W = Wq; bi = bq; C = Q;  }
    else if (blockIdx.z == 1) { W = Wk; bi = bk; C = Ko; }
    else                      { W = Wv; bi = bv; C = Vo; }
    gemm_body_tc(A, W, bi, nullptr, C, TT, DD, DD, 0);
}

// ---------------- flash attention: block = (qtile64, h, b), 256 threads ----------------
#define FST 68
__global__ __launch_bounds__(256) void flash_attn_kernel(const float* __restrict__ Q,
                                                         const float* __restrict__ Kc,
                                                         const float* __restrict__ Vc,
                                                         float* __restrict__ O) {
    extern __shared__ float sb[];
    float* Qt = sb;                     // [64][FST]  (d-major, scaled)
    float* Kt = Qt + 64 * FST;          // [64][FST]  (d-major)
    float* Vs = Kt + 64 * FST;          // [64][FST]  (k-major)
    float* Ps = Vs + 64 * FST;          // [64][FST]  (k-major: Ps[k][q])
    float* smx = Ps + 64 * FST;
    float* slx = smx + 64;
    float* sfx = slx + 64;

    int qt = blockIdx.x, h = blockIdx.y, b = blockIdx.z;
    int t = threadIdx.x;

    {
        int q = t & 63, d4 = t >> 6;
#pragma unroll
        for (int i = 0; i < 4; i++) {
            int dd4 = d4 + 4 * i;
            float4 f = *(const float4*)(Q + (size_t)(b * SS + qt * 64 + q) * DD + h * HD + dd4 * 4);
            Qt[(dd4 * 4 + 0) * FST + q] = f.x * 0.125f;
            Qt[(dd4 * 4 + 1) * FST + q] = f.y * 0.125f;
            Qt[(dd4 * 4 + 2) * FST + q] = f.z * 0.125f;
            Qt[(dd4 * 4 + 3) * FST + q] = f.w * 0.125f;
        }
    }
    if (t < 64) { smx[t] = -1e30f; slx[t] = 0.f; }

    float o[4][4];
#pragma unroll
    for (int i = 0; i < 4; i++)
#pragma unroll
        for (int j = 0; j < 4; j++) o[i][j] = 0.f;

    int qg = t & 15, kg = t >> 4;
    int qg2 = t >> 4, dg = t & 15;

    __syncthreads();

    for (int kt = 0; kt <= qt; kt++) {
        {
            int k = t & 63, d4 = t >> 6;
#pragma unroll
            for (int i = 0; i < 4; i++) {
                int dd4 = d4 + 4 * i;
                float4 f = *(const float4*)(Kc + (size_t)(b * SS + kt * 64 + k) * DD + h * HD + dd4 * 4);
                Kt[(dd4 * 4 + 0) * FST + k] = f.x;
                Kt[(dd4 * 4 + 1) * FST + k] = f.y;
                Kt[(dd4 * 4 + 2) * FST + k] = f.z;
                Kt[(dd4 * 4 + 3) * FST + k] = f.w;
            }
            int kv = t >> 4, dv4 = t & 15;
#pragma unroll
            for (int i = 0; i < 4; i++) {
                int kk = kv + 16 * i;
                float4 f = *(const float4*)(Vc + (size_t)(b * SS + kt * 64 + kk) * DD + h * HD + dv4 * 4);
                *(float4*)&Vs[kk * FST + dv4 * 4] = f;
            }
        }
        __syncthreads();

        float s[4][4];
#pragma unroll
        for (int i = 0; i < 4; i++)
#pragma unroll
            for (int j = 0; j < 4; j++) s[i][j] = 0.f;
        for (int d = 0; d < 64; d++) {
            float4 q4 = *(const float4*)&Qt[d * FST + qg * 4];
            float4 k4 = *(const float4*)&Kt[d * FST + kg * 4];
            float qa[4] = {q4.x, q4.y, q4.z, q4.w};
            float ka[4] = {k4.x, k4.y, k4.z, k4.w};
#pragma unroll
            for (int i = 0; i < 4; i++)
#pragma unroll
                for (int j = 0; j < 4; j++)
                    s[i][j] = fmaf(qa[i], ka[j], s[i][j]);
        }
        if (kt == qt) {
#pragma unroll
            for (int i = 0; i < 4; i++)
#pragma unroll
                for (int j = 0; j < 4; j++)
                    if (kg * 4 + j > qg * 4 + i) s[i][j] = -1e30f;
        }
#pragma unroll
        for (int j = 0; j < 4; j++)
#pragma unroll
            for (int i = 0; i < 4; i++)
                Ps[(kg * 4 + j) * FST + qg * 4 + i] = s[i][j];
        __syncthreads();

        if (t < 64) {
            int q = t;
            float m_old = smx[q];
            float tm = -1e30f;
            for (int k = 0; k < 64; k++) tm = fmaxf(tm, Ps[k * FST + q]);
            float mn = fmaxf(m_old, tm);
            float f = __expf(m_old - mn);
            float ssum = 0.f;
            for (int k = 0; k < 64; k++) {
                float pp = __expf(Ps[k * FST + q] - mn);
                Ps[k * FST + q] = pp;
                ssum += pp;
            }
            smx[q] = mn;
            slx[q] = slx[q] * f + ssum;
            sfx[q] = f;
        }
        __syncthreads();

        {
            float f0 = sfx[qg2 * 4 + 0], f1 = sfx[qg2 * 4 + 1];
            float f2 = sfx[qg2 * 4 + 2], f3 = sfx[qg2 * 4 + 3];
#pragma unroll
            for (int j = 0; j < 4; j++) {
                o[0][j] *= f0; o[1][j] *= f1; o[2][j] *= f2; o[3][j] *= f3;
            }
        }
        for (int k = 0; k < 64; k++) {
            float4 p4 = *(const float4*)&Ps[k * FST + qg2 * 4];
            float4 v4 = *(const float4*)&Vs[k * FST + dg * 4];
            float pa[4] = {p4.x, p4.y, p4.z, p4.w};
            float va[4] = {v4.x, v4.y, v4.z, v4.w};
#pragma unroll
            for (int i = 0; i < 4; i++)
#pragma unroll
                for (int j = 0; j < 4; j++)
                    o[i][j] = fmaf(pa[i], va[j], o[i][j]);
        }
        __syncthreads();
    }

#pragma unroll
    for (int i = 0; i < 4; i++) {
        int q = qg2 * 4 + i;
        float inv = 1.0f / slx[q];
        float4 f;
        f.x = o[i][0] * inv; f.y = o[i][1] * inv;
        f.z = o[i][2] * inv; f.w = o[i][3] * inv;
        *(float4*)(O + (size_t)(b * SS + qt * 64 + q) * DD + h * HD + dg * 4) = f;
    }
}

// ---------------- launch ----------------
extern "C" void kernel_launch(void* const* d_in, const int* in_sizes, int n_in,
                              void* d_out, int out_size) {
    const float* emb  = (const float*)d_in[0];
    const float* Wq   = (const float*)d_in[1];
    const float* bq   = (const float*)d_in[2];
    const float* Wk   = (const float*)d_in[3];
    const float* bk   = (const float*)d_in[4];
    const float* Wv   = (const float*)d_in[5];
    const float* bv   = (const float*)d_in[6];
    const float* Wo   = (const float*)d_in[7];
    const float* bo   = (const float*)d_in[8];
    const float* ln1g = (const float*)d_in[9];
    const float* ln1b = (const float*)d_in[10];
    const float* W1   = (const float*)d_in[11];
    const float* b1   = (const float*)d_in[12];
    const float* W2   = (const float*)d_in[13];
    const float* b2   = (const float*)d_in[14];
    const float* ln2g = (const float*)d_in[15];
    const float* ln2b = (const float*)d_in[16];
    const float* lnfg = (const float*)d_in[17];
    const float* lnfb = (const float*)d_in[18];
    const float* Wout = (const float*)d_in[19];
    const int*   ids  = (const int*)d_in[20];

    float *x, *h, *q, *k, *v, *at, *ff;
    cudaGetSymbolAddress((void**)&x,  g_x);
    cudaGetSymbolAddress((void**)&h,  g_h);
    cudaGetSymbolAddress((void**)&q,  g_q);
    cudaGetSymbolAddress((void**)&k,  g_k);
    cudaGetSymbolAddress((void**)&v,  g_v);
    cudaGetSymbolAddress((void**)&at, g_at);
    cudaGetSymbolAddress((void**)&ff, g_ff);

    static int attr_set = 0;
    const int flash_smem = (4 * 64 * FST + 3 * 64) * 4;
    if (!attr_set) {
        cudaFuncSetAttribute(flash_attn_kernel,
                             cudaFuncAttributeMaxDynamicSharedMemorySize, flash_smem);
        cudaFuncSetAttribute(sgemm_kernel,
                             cudaFuncAttributeMaxDynamicSharedMemorySize, GEMM_SMEM);
        cudaFuncSetAttribute(sgemm_qkv_kernel,
                             cudaFuncAttributeMaxDynamicSharedMemorySize, GEMM_SMEM);
        attr_set = 1;
    }

    embed_kernel<<<(TT * DD) / 256, 256>>>(emb, ids, x);

    dim3 gN1(DD / 128, TT / 128);        // (8, 16)
    dim3 gQKV(DD / 128, TT / 128, 3);    // (8, 16, 3)
    dim3 gFF1(FFD / 128, TT / 128);      // (32, 16)
    dim3 gOut(VV / 128, TT / 128);       // (250, 16)
    dim3 gAttn(SS / 64, HH, BB);         // (16, 16, 2)

    for (int l = 0; l < LL; l++) {
        size_t woff = (size_t)l * DD * DD;
        ln_kernel<<<TT, 256>>>(x, ln1g + l * DD, ln1b + l * DD, h);
        sgemm_qkv_kernel<<<gQKV, 256, GEMM_SMEM>>>(h, Wq + woff, Wk + woff, Wv + woff,
                                                   bq + l * DD, bk + l * DD, bv + l * DD,
                                                   q, k, v);
        flash_attn_kernel<<<gAttn, 256, flash_smem>>>(q, k, v, at);
        sgemm_kernel<<<gN1, 256, GEMM_SMEM>>>(at, Wo + woff, bo + l * DD, x, x,
                                              TT, DD, DD, 0);
        ln_kernel<<<TT, 256>>>(x, ln2g + l * DD, ln2b + l * DD, h);
        sgemm_kernel<<<gFF1, 256, GEMM_SMEM>>>(h, W1 + (size_t)l * DD * FFD, b1 + l * FFD,
                                               nullptr, ff, TT, FFD, DD, 1);
        sgemm_kernel<<<gN1, 256, GEMM_SMEM>>>(ff, W2 + (size_t)l * FFD * DD, b2 + l * DD,
                                              x, x, TT, DD, FFD, 0);
    }
    ln_kernel<<<TT, 256>>>(x, lnfg, lnfb, h);
    sgemm_kernel<<<gOut, 256, GEMM_SMEM>>>(h, Wout, nullptr, nullptr, (float*)d_out,
                                           TT, VV, DD, 0);
}

// round 10
// speedup vs baseline: 1.5126x; 1.5126x over previous
#include <cuda_runtime.h>
#include <cuda_bf16.h>
#include <math.h>
#include <stdint.h>

#define TT 2048      // B*S tokens
#define DD 1024      // model dim
#define FFD 4096     // ff dim
#define VV 32000     // vocab
#define HH 16        // heads
#define HD 64        // head dim
#define LL 6         // layers
#define SS 1024      // seq len
#define BB 2         // batch

// ---------------- scratch (no allocation allowed) ----------------
__device__ float g_x[TT * DD];
__device__ float g_h[TT * DD];
__device__ float g_q[TT * DD];
__device__ float g_k[TT * DD];
__device__ float g_v[TT * DD];
__device__ float g_at[TT * DD];
__device__ float g_ff[TT * FFD];

// ---------------- embedding + sinusoidal positional encoding ----------------
__global__ void embed_kernel(const float* __restrict__ emb,
                             const int* __restrict__ ids,
                             float* __restrict__ x) {
    int idx = blockIdx.x * 256 + threadIdx.x;
    if (idx >= TT * DD) return;
    int t = idx >> 10;
    int d = idx & (DD - 1);
    int pos = t & (SS - 1);
    float val = emb[ids[t] * DD + d] * 32.0f;
    float ang = (float)pos * expf((float)(d & ~1) * (-9.210340371976184f / 1024.0f));
    val += (d & 1) ? cosf(ang) : sinf(ang);
    x[idx] = val;
}

// ---------------- layernorm ----------------
__global__ __launch_bounds__(256) void ln_kernel(const float* __restrict__ x,
                                                 const float* __restrict__ g,
                                                 const float* __restrict__ bta,
                                                 float* __restrict__ out) {
    int row = blockIdx.x;
    const float* xr = x + (size_t)row * DD;
    float s1 = 0.f, s2 = 0.f;
    for (int i = threadIdx.x; i < DD; i += 256) {
        float v = xr[i];
        s1 += v;
        s2 = fmaf(v, v, s2);
    }
    for (int o = 16; o; o >>= 1) {
        s1 += __shfl_xor_sync(0xffffffffu, s1, o);
        s2 += __shfl_xor_sync(0xffffffffu, s2, o);
    }
    __shared__ float r1[8], r2[8];
    __shared__ float smean, srstd;
    int w = threadIdx.x >> 5, lane = threadIdx.x & 31;
    if (lane == 0) { r1[w] = s1; r2[w] = s2; }
    __syncthreads();
    if (threadIdx.x == 0) {
        float t1 = 0.f, t2 = 0.f;
        for (int i = 0; i < 8; i++) { t1 += r1[i]; t2 += r2[i]; }
        float mean = t1 * (1.0f / DD);
        float var  = t2 * (1.0f / DD) - mean * mean;
        smean = mean;
        srstd = rsqrtf(var + 1e-5f);
    }
    __syncthreads();
    float mean = smean, rstd = srstd;
    for (int i = threadIdx.x; i < DD; i += 256)
        out[(size_t)row * DD + i] = (xr[i] - mean) * rstd * g[i] + bta[i];
}

// ---------------- bf16 split helpers ----------------
// Split two floats (consecutive k) into packed bf16x2 hi and lo words.
// hi word = {low16 = bf16(f0), high16 = bf16(f1)}  (k-ascending, MMA order)
__device__ __forceinline__ void split_bf16x2(float f0, float f1,
                                             uint32_t& hi, uint32_t& lo) {
    uint32_t h;
    asm("cvt.rn.bf16x2.f32 %0, %1, %2;" : "=r"(h) : "f"(f1), "f"(f0));
    float h0 = __uint_as_float(h << 16);
    float h1 = __uint_as_float(h & 0xffff0000u);
    float l0 = f0 - h0;
    float l1 = f1 - h1;
    uint32_t l;
    asm("cvt.rn.bf16x2.f32 %0, %1, %2;" : "=r"(l) : "f"(l1), "f"(l0));
    hi = h; lo = l;
}

__device__ __forceinline__ void mma_bf16(float* c, const uint32_t* a, const uint32_t* b) {
    asm volatile(
        "mma.sync.aligned.m16n8k16.row.col.f32.bf16.bf16.f32 "
        "{%0,%1,%2,%3}, {%4,%5,%6,%7}, {%8,%9}, {%0,%1,%2,%3};\n"
        : "+f"(c[0]), "+f"(c[1]), "+f"(c[2]), "+f"(c[3])
        : "r"(a[0]), "r"(a[1]), "r"(a[2]), "r"(a[3]), "r"(b[0]), "r"(b[1]));
}

// ---------------- bf16x3 tensor-core GEMM: 128x128x32 tiles ----------------
// smem: per k-PAIR (2 k values) per element store float2 = (hi bf16x2, lo bf16x2).
// 16 kpair-rows per 32-K tile. Double-buffered; 2 CTAs/SM.
// C[M,N] = A[M,K] @ B[K,N] (+bias)(gelu?)(+res). M%128==0, N%128==0, K%32==0.
#define S2 132                        // float2 row stride (row step = 8 banks)
#define KP 16                         // kpair rows per tile
#define BUF_F2 (2 * KP * S2)          // A + B per buffer (float2 count)
#define GEMM_SMEM (2 * BUF_F2 * 8)    // bytes = 67584 (double-buffered)

__device__ __forceinline__ void gemm_body_tc(const float* __restrict__ A,
                                             const float* __restrict__ Bw,
                                             const float* __restrict__ bias,
                                             const float* __restrict__ res,
                                             float* __restrict__ C,
                                             int M, int N, int K, int gelu) {
    extern __shared__ float2 sm2[];
    int t = threadIdx.x;
    int bm = blockIdx.y, bn = blockIdx.x;
    int w = t >> 5, lane = t & 31;
    int wm = w >> 2, wn = w & 3;                 // warps: 2(m) x 4(n)
    int m_base = wm * 64, n_base = wn * 32;
    int gid = lane >> 2, tig = lane & 3;

    // A loader: m = t&127 fixed; float4 covers k4*4..+3 = kpairs 2k4, 2k4+1
    int am = t & 127;
    int ak4 = t >> 7;                 // 0/1, +2 per iter -> k4 in 0..7
    const float* Arow = A + (size_t)(bm * 128 + am) * K;
    // B loader: n-pair = t&63, kpair base = t>>6 (0..3), +4 per iter
    int bn2 = t & 63;
    int bkp = t >> 6;
    const float* Bbase = Bw + bn * 128 + bn2 * 2;

    float acc[4][4][4];
#pragma unroll
    for (int mf = 0; mf < 4; mf++)
#pragma unroll
        for (int nf = 0; nf < 4; nf++)
#pragma unroll
            for (int r = 0; r < 4; r++) acc[mf][nf][r] = 0.f;

    int ntiles = K >> 5;
    float4 ra[4];
    float2 rb0[4], rb1[4];

    // ---- load tile 0 ----
#pragma unroll
    for (int i = 0; i < 4; i++) {
        ra[i] = *(const float4*)(Arow + (ak4 + 2 * i) * 4);
        int kk = 2 * (bkp + 4 * i);
        rb0[i] = *(const float2*)(Bbase + (size_t)kk * N);
        rb1[i] = *(const float2*)(Bbase + (size_t)(kk + 1) * N);
    }
    // ---- split+store tile 0 into buffer 0 ----
    {
        float2* Ah = sm2;
        float2* Bh = sm2 + KP * S2;
#pragma unroll
        for (int i = 0; i < 4; i++) {
            int k4 = ak4 + 2 * i;
            uint32_t h0, l0, h1, l1;
            split_bf16x2(ra[i].x, ra[i].y, h0, l0);
            split_bf16x2(ra[i].z, ra[i].w, h1, l1);
            Ah[(2 * k4) * S2 + am]     = make_float2(__uint_as_float(h0), __uint_as_float(l0));
            Ah[(2 * k4 + 1) * S2 + am] = make_float2(__uint_as_float(h1), __uint_as_float(l1));
            int kp = bkp + 4 * i;
            uint32_t hA, lA, hB, lB;
            split_bf16x2(rb0[i].x, rb1[i].x, hA, lA);   // n even
            split_bf16x2(rb0[i].y, rb1[i].y, hB, lB);   // n odd
            float4 st;
            st.x = __uint_as_float(hA); st.y = __uint_as_float(lA);
            st.z = __uint_as_float(hB); st.w = __uint_as_float(lB);
            *(float4*)&Bh[kp * S2 + 2 * bn2] = st;
        }
    }
    __syncthreads();

    int p = 0;
    for (int tt = 0; tt < ntiles; tt++) {
        bool more = (tt + 1) < ntiles;
        if (more) {
            int k0 = (tt + 1) << 5;
#pragma unroll
            for (int i = 0; i < 4; i++) {
                ra[i] = *(const float4*)(Arow + k0 + (ak4 + 2 * i) * 4);
                int kk = k0 + 2 * (bkp + 4 * i);
                rb0[i] = *(const float2*)(Bbase + (size_t)kk * N);
                rb1[i] = *(const float2*)(Bbase + (size_t)(kk + 1) * N);
            }
        }

        // ---- compute on buffer p: two k16 slices ----
        const float2* Ah = sm2 + p * BUF_F2;
        const float2* Bh = Ah + KP * S2;
#pragma unroll
        for (int ks2 = 0; ks2 < KP; ks2 += 8) {
            uint32_t bhi[4][2], blo[4][2];
#pragma unroll
            for (int nf = 0; nf < 4; nf++) {
                int nn = n_base + nf * 8 + gid;
                float2 p0 = Bh[(ks2 + tig) * S2 + nn];
                float2 p1 = Bh[(ks2 + tig + 4) * S2 + nn];
                bhi[nf][0] = __float_as_uint(p0.x);
                blo[nf][0] = __float_as_uint(p0.y);
                bhi[nf][1] = __float_as_uint(p1.x);
                blo[nf][1] = __float_as_uint(p1.y);
            }
#pragma unroll
            for (int mf = 0; mf < 4; mf++) {
                int mc = m_base + mf * 16 + gid;
                float2 a0 = Ah[(ks2 + tig) * S2 + mc];
                float2 a1 = Ah[(ks2 + tig) * S2 + mc + 8];
                float2 a2 = Ah[(ks2 + tig + 4) * S2 + mc];
                float2 a3 = Ah[(ks2 + tig + 4) * S2 + mc + 8];
                uint32_t ahi[4] = {__float_as_uint(a0.x), __float_as_uint(a1.x),
                                   __float_as_uint(a2.x), __float_as_uint(a3.x)};
                uint32_t alo[4] = {__float_as_uint(a0.y), __float_as_uint(a1.y),
                                   __float_as_uint(a2.y), __float_as_uint(a3.y)};
#pragma unroll
                for (int nf = 0; nf < 4; nf++) mma_bf16(acc[mf][nf], ahi, bhi[nf]);
#pragma unroll
                for (int nf = 0; nf < 4; nf++) mma_bf16(acc[mf][nf], ahi, blo[nf]);
#pragma unroll
                for (int nf = 0; nf < 4; nf++) mma_bf16(acc[mf][nf], alo, bhi[nf]);
            }
        }

        // ---- split+store next tile into buffer p^1 (other buffer: no wait) ----
        if (more) {
            float2* An = sm2 + (p ^ 1) * BUF_F2;
            float2* Bn = An + KP * S2;
#pragma unroll
            for (int i = 0; i < 4; i++) {
                int k4 = ak4 + 2 * i;
                uint32_t h0, l0, h1, l1;
                split_bf16x2(ra[i].x, ra[i].y, h0, l0);
                split_bf16x2(ra[i].z, ra[i].w, h1, l1);
                An[(2 * k4) * S2 + am]     = make_float2(__uint_as_float(h0), __uint_as_float(l0));
                An[(2 * k4 + 1) * S2 + am] = make_float2(__uint_as_float(h1), __uint_as_float(l1));
                int kp = bkp + 4 * i;
                uint32_t hA, lA, hB, lB;
                split_bf16x2(rb0[i].x, rb1[i].x, hA, lA);
                split_bf16x2(rb0[i].y, rb1[i].y, hB, lB);
                float4 st;
                st.x = __uint_as_float(hA); st.y = __uint_as_float(lA);
                st.z = __uint_as_float(hB); st.w = __uint_as_float(lB);
                *(float4*)&Bn[kp * S2 + 2 * bn2] = st;
            }
        }
        __syncthreads();
        p ^= 1;
    }

    // ---- epilogue: paired float2 stores ----
#pragma unroll
    for (int mf = 0; mf < 4; mf++) {
        int row0 = bm * 128 + m_base + mf * 16 + gid;
#pragma unroll
        for (int nf = 0; nf < 4; nf++) {
            int col = bn * 128 + n_base + nf * 8 + tig * 2;
            float bx = 0.f, by = 0.f;
            if (bias) { bx = bias[col]; by = bias[col + 1]; }
#pragma unroll
            for (int half = 0; half < 2; half++) {
                int row = row0 + half * 8;
                float vx = acc[mf][nf][half * 2 + 0] + bx;
                float vy = acc[mf][nf][half * 2 + 1] + by;
                if (gelu) {
                    vx = 0.5f * vx * (1.0f + erff(vx * 0.70710678118654752f));
                    vy = 0.5f * vy * (1.0f + erff(vy * 0.70710678118654752f));
                }
                size_t o = (size_t)row * N + col;
                if (res) {
                    float2 rr = *(const float2*)(res + o);
                    vx += rr.x; vy += rr.y;
                }
                float2 ov; ov.x = vx; ov.y = vy;
                *(float2*)(C + o) = ov;
            }
        }
    }
}

__global__ __launch_bounds__(256, 2) void sgemm_kernel(const float* A, const float* Bw,
                                                       const float* bias, const float* res,
                                                       float* C, int M, int N, int K, int gelu) {
    gemm_body_tc(A, Bw, bias, res, C, M, N, K, gelu);
}

__global__ __launch_bounds__(256, 2) void sgemm_qkv_kernel(const float* A,
                                                           const float* Wq, const float* Wk, const float* Wv,
                                                           const float* bq, const float* bk, const float* bv,
                                                           float* Q, float* Ko, float* Vo) {
    const float* W; const float* bi; float* C;
    if (blockIdx.z == 0)      { W = Wq; bi = bq; C = Q;  }
    else if (blockIdx.z == 1) { W = Wk; bi = bk; C = Ko; }
    else                      { W = Wv; bi = bv; C = Vo; }
    gemm_body_tc(A, W, bi, nullptr, C, TT, DD, DD, 0);
}

// ---------------- flash attention: block = (qtile64, h, b), 256 threads ----------------
#define FST 68
__global__ __launch_bounds__(256) void flash_attn_kernel(const float* __restrict__ Q,
                                                         const float* __restrict__ Kc,
                                                         const float* __restrict__ Vc,
                                                         float* __restrict__ O) {
    extern __shared__ float sb[];
    float* Qt = sb;                     // [64][FST]  (d-major, scaled)
    float* Kt = Qt + 64 * FST;          // [64][FST]  (d-major)
    float* Vs = Kt + 64 * FST;          // [64][FST]  (k-major)
    float* Ps = Vs + 64 * FST;          // [64][FST]  (k-major: Ps[k][q])
    float* smx = Ps + 64 * FST;
    float* slx = smx + 64;
    float* sfx = slx + 64;

    int qt = blockIdx.x, h = blockIdx.y, b = blockIdx.z;
    int t = threadIdx.x;

    {
        int q = t & 63, d4 = t >> 6;
#pragma unroll
        for (int i = 0; i < 4; i++) {
            int dd4 = d4 + 4 * i;
            float4 f = *(const float4*)(Q + (size_t)(b * SS + qt * 64 + q) * DD + h * HD + dd4 * 4);
            Qt[(dd4 * 4 + 0) * FST + q] = f.x * 0.125f;
            Qt[(dd4 * 4 + 1) * FST + q] = f.y * 0.125f;
            Qt[(dd4 * 4 + 2) * FST + q] = f.z * 0.125f;
            Qt[(dd4 * 4 + 3) * FST + q] = f.w * 0.125f;
        }
    }
    if (t < 64) { smx[t] = -1e30f; slx[t] = 0.f; }

    float o[4][4];
#pragma unroll
    for (int i = 0; i < 4; i++)
#pragma unroll
        for (int j = 0; j < 4; j++) o[i][j] = 0.f;

    int qg = t & 15, kg = t >> 4;
    int qg2 = t >> 4, dg = t & 15;

    __syncthreads();

    for (int kt = 0; kt <= qt; kt++) {
        {
            int k = t & 63, d4 = t >> 6;
#pragma unroll
            for (int i = 0; i < 4; i++) {
                int dd4 = d4 + 4 * i;
                float4 f = *(const float4*)(Kc + (size_t)(b * SS + kt * 64 + k) * DD + h * HD + dd4 * 4);
                Kt[(dd4 * 4 + 0) * FST + k] = f.x;
                Kt[(dd4 * 4 + 1) * FST + k] = f.y;
                Kt[(dd4 * 4 + 2) * FST + k] = f.z;
                Kt[(dd4 * 4 + 3) * FST + k] = f.w;
            }
            int kv = t >> 4, dv4 = t & 15;
#pragma unroll
            for (int i = 0; i < 4; i++) {
                int kk = kv + 16 * i;
                float4 f = *(const float4*)(Vc + (size_t)(b * SS + kt * 64 + kk) * DD + h * HD + dv4 * 4);
                *(float4*)&Vs[kk * FST + dv4 * 4] = f;
            }
        }
        __syncthreads();

        float s[4][4];
#pragma unroll
        for (int i = 0; i < 4; i++)
#pragma unroll
            for (int j = 0; j < 4; j++) s[i][j] = 0.f;
        for (int d = 0; d < 64; d++) {
            float4 q4 = *(const float4*)&Qt[d * FST + qg * 4];
            float4 k4 = *(const float4*)&Kt[d * FST + kg * 4];
            float qa[4] = {q4.x, q4.y, q4.z, q4.w};
            float ka[4] = {k4.x, k4.y, k4.z, k4.w};
#pragma unroll
            for (int i = 0; i < 4; i++)
#pragma unroll
                for (int j = 0; j < 4; j++)
                    s[i][j] = fmaf(qa[i], ka[j], s[i][j]);
        }
        if (kt == qt) {
#pragma unroll
            for (int i = 0; i < 4; i++)
#pragma unroll
                for (int j = 0; j < 4; j++)
                    if (kg * 4 + j > qg * 4 + i) s[i][j] = -1e30f;
        }
#pragma unroll
        for (int j = 0; j < 4; j++)
#pragma unroll
            for (int i = 0; i < 4; i++)
                Ps[(kg * 4 + j) * FST + qg * 4 + i] = s[i][j];
        __syncthreads();

        if (t < 64) {
            int q = t;
            float m_old = smx[q];
            float tm = -1e30f;
            for (int k = 0; k < 64; k++) tm = fmaxf(tm, Ps[k * FST + q]);
            float mn = fmaxf(m_old, tm);
            float f = __expf(m_old - mn);
            float ssum = 0.f;
            for (int k = 0; k < 64; k++) {
                float pp = __expf(Ps[k * FST + q] - mn);
                Ps[k * FST + q] = pp;
                ssum += pp;
            }
            smx[q] = mn;
            slx[q] = slx[q] * f + ssum;
            sfx[q] = f;
        }
        __syncthreads();

        {
            float f0 = sfx[qg2 * 4 + 0], f1 = sfx[qg2 * 4 + 1];
            float f2 = sfx[qg2 * 4 + 2], f3 = sfx[qg2 * 4 + 3];
#pragma unroll
            for (int j = 0; j < 4; j++) {
                o[0][j] *= f0; o[1][j] *= f1; o[2][j] *= f2; o[3][j] *= f3;
            }
        }
        for (int k = 0; k < 64; k++) {
            float4 p4 = *(const float4*)&Ps[k * FST + qg2 * 4];
            float4 v4 = *(const float4*)&Vs[k * FST + dg * 4];
            float pa[4] = {p4.x, p4.y, p4.z, p4.w};
            float va[4] = {v4.x, v4.y, v4.z, v4.w};
#pragma unroll
            for (int i = 0; i < 4; i++)
#pragma unroll
                for (int j = 0; j < 4; j++)
                    o[i][j] = fmaf(pa[i], va[j], o[i][j]);
        }
        __syncthreads();
    }

#pragma unroll
    for (int i = 0; i < 4; i++) {
        int q = qg2 * 4 + i;
        float inv = 1.0f / slx[q];
        float4 f;
        f.x = o[i][0] * inv; f.y = o[i][1] * inv;
        f.z = o[i][2] * inv; f.w = o[i][3] * inv;
        *(float4*)(O + (size_t)(b * SS + qt * 64 + q) * DD + h * HD + dg * 4) = f;
    }
}

// ---------------- launch ----------------
extern "C" void kernel_launch(void* const* d_in, const int* in_sizes, int n_in,
                              void* d_out, int out_size) {
    const float* emb  = (const float*)d_in[0];
    const float* Wq   = (const float*)d_in[1];
    const float* bq   = (const float*)d_in[2];
    const float* Wk   = (const float*)d_in[3];
    const float* bk   = (const float*)d_in[4];
    const float* Wv   = (const float*)d_in[5];
    const float* bv   = (const float*)d_in[6];
    const float* Wo   = (const float*)d_in[7];
    const float* bo   = (const float*)d_in[8];
    const float* ln1g = (const float*)d_in[9];
    const float* ln1b = (const float*)d_in[10];
    const float* W1   = (const float*)d_in[11];
    const float* b1   = (const float*)d_in[12];
    const float* W2   = (const float*)d_in[13];
    const float* b2   = (const float*)d_in[14];
    const float* ln2g = (const float*)d_in[15];
    const float* ln2b = (const float*)d_in[16];
    const float* lnfg = (const float*)d_in[17];
    const float* lnfb = (const float*)d_in[18];
    const float* Wout = (const float*)d_in[19];
    const int*   ids  = (const int*)d_in[20];

    float *x, *h, *q, *k, *v, *at, *ff;
    cudaGetSymbolAddress((void**)&x,  g_x);
    cudaGetSymbolAddress((void**)&h,  g_h);
    cudaGetSymbolAddress((void**)&q,  g_q);
    cudaGetSymbolAddress((void**)&k,  g_k);
    cudaGetSymbolAddress((void**)&v,  g_v);
    cudaGetSymbolAddress((void**)&at, g_at);
    cudaGetSymbolAddress((void**)&ff, g_ff);

    static int attr_set = 0;
    const int flash_smem = (4 * 64 * FST + 3 * 64) * 4;
    if (!attr_set) {
        cudaFuncSetAttribute(flash_attn_kernel,
                             cudaFuncAttributeMaxDynamicSharedMemorySize, flash_smem);
        cudaFuncSetAttribute(sgemm_kernel,
                             cudaFuncAttributeMaxDynamicSharedMemorySize, GEMM_SMEM);
        cudaFuncSetAttribute(sgemm_qkv_kernel,
                             cudaFuncAttributeMaxDynamicSharedMemorySize, GEMM_SMEM);
        attr_set = 1;
    }

    embed_kernel<<<(TT * DD) / 256, 256>>>(emb, ids, x);

    dim3 gN1(DD / 128, TT / 128);        // (8, 16)
    dim3 gQKV(DD / 128, TT / 128, 3);    // (8, 16, 3)
    dim3 gFF1(FFD / 128, TT / 128);      // (32, 16)
    dim3 gOut(VV / 128, TT / 128);       // (250, 16)
    dim3 gAttn(SS / 64, HH, BB);         // (16, 16, 2)

    for (int l = 0; l < LL; l++) {
        size_t woff = (size_t)l * DD * DD;
        ln_kernel<<<TT, 256>>>(x, ln1g + l * DD, ln1b + l * DD, h);
        sgemm_qkv_kernel<<<gQKV, 256, GEMM_SMEM>>>(h, Wq + woff, Wk + woff, Wv + woff,
                                                   bq + l * DD, bk + l * DD, bv + l * DD,
                                                   q, k, v);
        flash_attn_kernel<<<gAttn, 256, flash_smem>>>(q, k, v, at);
        sgemm_kernel<<<gN1, 256, GEMM_SMEM>>>(at, Wo + woff, bo + l * DD, x, x,
                                              TT, DD, DD, 0);
        ln_kernel<<<TT, 256>>>(x, ln2g + l * DD, ln2b + l * DD, h);
        sgemm_kernel<<<gFF1, 256, GEMM_SMEM>>>(h, W1 + (size_t)l * DD * FFD, b1 + l * FFD,
                                               nullptr, ff, TT, FFD, DD, 1);
        sgemm_kernel<<<gN1, 256, GEMM_SMEM>>>(ff, W2 + (size_t)l * FFD * DD, b2 + l * DD,
                                              x, x, TT, DD, FFD, 0);
    }
    ln_kernel<<<TT, 256>>>(x, lnfg, lnfb, h);
    sgemm_kernel<<<gOut, 256, GEMM_SMEM>>>(h, Wout, nullptr, nullptr, (float*)d_out,
                                           TT, VV, DD, 0);
}

// round 12
// speedup vs baseline: 2.3710x; 1.5675x over previous
#include <cuda_runtime.h>
#include <cuda_bf16.h>
#include <math.h>
#include <stdint.h>

#define TT 2048      // B*S tokens
#define DD 1024      // model dim
#define FFD 4096     // ff dim
#define VV 32000     // vocab
#define HH 16        // heads
#define HD 64        // head dim
#define LL 6         // layers
#define SS 1024      // seq len
#define BB 2         // batch

// ---------------- weight scratch offsets (elements) ----------------
#define OFF_WQ   0ULL
#define OFF_WK   (OFF_WQ + 6ULL * 1024 * 1024)
#define OFF_WV   (OFF_WK + 6ULL * 1024 * 1024)
#define OFF_WO   (OFF_WV + 6ULL * 1024 * 1024)
#define OFF_W1   (OFF_WO + 6ULL * 1024 * 1024)
#define OFF_W2   (OFF_W1 + 6ULL * 1024 * 4096)
#define OFF_WOUT (OFF_W2 + 6ULL * 4096 * 1024)
#define W_TOTAL  (OFF_WOUT + 1024ULL * 32000)

// ---------------- scratch (no allocation allowed) ----------------
__device__ __nv_bfloat16 g_whi[W_TOTAL];
__device__ __nv_bfloat16 g_wlo[W_TOTAL];
__device__ float g_x[TT * DD];
__device__ float g_q[TT * DD];
__device__ float g_k[TT * DD];
__device__ float g_v[TT * DD];
__device__ __nv_bfloat16 g_hhi[TT * DD];
__device__ __nv_bfloat16 g_hlo[TT * DD];
__device__ __nv_bfloat16 g_athi[TT * DD];
__device__ __nv_bfloat16 g_atlo[TT * DD];
__device__ __nv_bfloat16 g_ffhi[TT * FFD];
__device__ __nv_bfloat16 g_fflo[TT * FFD];

// ---------------- baseline-PTX helpers (NO arch-specific instructions) ----------------
__device__ __forceinline__ uint32_t smem_u32(const void* p) {
    uint32_t a;
    asm("{ .reg .u64 t; cvta.to.shared.u64 t, %1; cvt.u32.u64 %0, t; }" : "=r"(a) : "l"(p));
    return a;
}
#define CP_ASYNC16(dst, src) \
    asm volatile("cp.async.cg.shared.global [%0], [%1], 16;" :: "r"(dst), "l"(src))
#define CP_COMMIT() asm volatile("cp.async.commit_group;" ::: "memory")
#define CP_WAIT0()  asm volatile("cp.async.wait_group 0;" ::: "memory")
#define LDSM4(r0, r1, r2, r3, a) \
    asm volatile("ldmatrix.sync.aligned.m8n8.x4.shared.b16 {%0,%1,%2,%3}, [%4];" \
                 : "=r"(r0), "=r"(r1), "=r"(r2), "=r"(r3) : "r"(a))

__device__ __forceinline__ void mma_bf16(float* c, const uint32_t* a, const uint32_t* b) {
    asm volatile(
        "mma.sync.aligned.m16n8k16.row.col.f32.bf16.bf16.f32 "
        "{%0,%1,%2,%3}, {%4,%5,%6,%7}, {%8,%9}, {%0,%1,%2,%3};\n"
        : "+f"(c[0]), "+f"(c[1]), "+f"(c[2]), "+f"(c[3])
        : "r"(a[0]), "r"(a[1]), "r"(a[2]), "r"(a[3]), "r"(b[0]), "r"(b[1]));
}

__device__ __forceinline__ void fsplit(float v, __nv_bfloat16& h, __nv_bfloat16& l) {
    h = __float2bfloat16(v);
    l = __float2bfloat16(v - __bfloat162float(h));
}

// ---------------- weight transpose+split: [K,N] fp32 -> [N,K] bf16 hi/lo ----------------
__global__ __launch_bounds__(256) void tsplit_kernel(const float* __restrict__ src,
                                                     __nv_bfloat16* __restrict__ dhi,
                                                     __nv_bfloat16* __restrict__ dlo,
                                                     int K, int N) {
    __shared__ float s[32][33];
    size_t zo = (size_t)blockIdx.z * K * N;
    src += zo; dhi += zo; dlo += zo;
    int n0 = blockIdx.x * 32, k0 = blockIdx.y * 32;
    int tx = threadIdx.x & 31, ty = threadIdx.x >> 5;   // 32 x 8
#pragma unroll
    for (int i = 0; i < 4; i++)
        s[ty + 8 * i][tx] = src[(size_t)(k0 + ty + 8 * i) * N + n0 + tx];
    __syncthreads();
#pragma unroll
    for (int i = 0; i < 4; i++) {
        int n = n0 + ty + 8 * i, k = k0 + tx;
        float v = s[tx][ty + 8 * i];
        __nv_bfloat16 h, l;
        fsplit(v, h, l);
        dhi[(size_t)n * K + k] = h;
        dlo[(size_t)n * K + k] = l;
    }
}

// ---------------- embedding + positional encoding ----------------
__global__ void embed_kernel(const float* __restrict__ emb,
                             const int* __restrict__ ids,
                             float* __restrict__ x) {
    int idx = blockIdx.x * 256 + threadIdx.x;
    if (idx >= TT * DD) return;
    int t = idx >> 10;
    int d = idx & (DD - 1);
    int pos = t & (SS - 1);
    float val = emb[ids[t] * DD + d] * 32.0f;
    float ang = (float)pos * expf((float)(d & ~1) * (-9.210340371976184f / 1024.0f));
    val += (d & 1) ? cosf(ang) : sinf(ang);
    x[idx] = val;
}

// ---------------- layernorm -> split bf16 output ----------------
__global__ __launch_bounds__(256) void ln_kernel(const float* __restrict__ x,
                                                 const float* __restrict__ g,
                                                 const float* __restrict__ bta,
                                                 __nv_bfloat16* __restrict__ ohi,
                                                 __nv_bfloat16* __restrict__ olo) {
    int row = blockIdx.x;
    const float* xr = x + (size_t)row * DD;
    float s1 = 0.f, s2 = 0.f;
    for (int i = threadIdx.x; i < DD; i += 256) {
        float v = xr[i];
        s1 += v;
        s2 = fmaf(v, v, s2);
    }
    for (int o = 16; o; o >>= 1) {
        s1 += __shfl_xor_sync(0xffffffffu, s1, o);
        s2 += __shfl_xor_sync(0xffffffffu, s2, o);
    }
    __shared__ float r1[8], r2[8];
    __shared__ float smean, srstd;
    int w = threadIdx.x >> 5, lane = threadIdx.x & 31;
    if (lane == 0) { r1[w] = s1; r2[w] = s2; }
    __syncthreads();
    if (threadIdx.x == 0) {
        float t1 = 0.f, t2 = 0.f;
        for (int i = 0; i < 8; i++) { t1 += r1[i]; t2 += r2[i]; }
        float mean = t1 * (1.0f / DD);
        float var  = t2 * (1.0f / DD) - mean * mean;
        smean = mean;
        srstd = rsqrtf(var + 1e-5f);
    }
    __syncthreads();
    float mean = smean, rstd = srstd;
    for (int i = threadIdx.x; i < DD; i += 256) {
        float v = (xr[i] - mean) * rstd * g[i] + bta[i];
        __nv_bfloat16 h, l;
        fsplit(v, h, l);
        ohi[(size_t)row * DD + i] = h;
        olo[(size_t)row * DD + i] = l;
    }
}

// ---------------- bf16x3 mma.sync GEMM with cp.async + ldmatrix ----------------
// A pre-split bf16 [M,K] hi/lo; B pre-split bf16 [N,K] hi/lo (W^T).
// 128x128 tile, 256 thr, BK=32, double-buffered cp.async, 2 CTAs/SM.
#define TST 80                        // smem tile row stride (bytes): 20-bank step
#define TILE_B (128 * TST)            // 10240 B per tile
#define BUF_B (4 * TILE_B)            // Ah, Al, Bh, Bl
#define GEMM_SMEM (2 * BUF_B)         // 81920 B double-buffered

__device__ __forceinline__ void gemm12_body(
    const __nv_bfloat16* __restrict__ Ahg, const __nv_bfloat16* __restrict__ Alg,
    const __nv_bfloat16* __restrict__ Bhg, const __nv_bfloat16* __restrict__ Blg,
    const float* __restrict__ bias, const float* __restrict__ res,
    float* __restrict__ Cf, __nv_bfloat16* __restrict__ Chi, __nv_bfloat16* __restrict__ Clo,
    int N, int K, char* smem)
{
    uint32_t sbase = smem_u32(smem);
    int t = threadIdx.x, w = t >> 5, l = t & 31;
    int bm = blockIdx.y, bn = blockIdx.x;
    int wm = w >> 2, wn = w & 3;               // warps 2(m) x 4(n)
    int m_base = wm * 64, n_base = wn * 32;

    // loader mapping: per warp 8 rows x 4 chunks; 2 row-iterations
    int lrow = w * 8 + (l & 7);
    int lc = l >> 3;                            // chunk 0..3 (8 bf16 each)
    const __nv_bfloat16* gsrc[4] = {Ahg, Alg, Bhg, Blg};

    float acc[4][4][4];
#pragma unroll
    for (int mf = 0; mf < 4; mf++)
#pragma unroll
        for (int nf = 0; nf < 4; nf++)
#pragma unroll
            for (int r = 0; r < 4; r++) acc[mf][nf][r] = 0.f;

    int S = K >> 5;

    auto load_stage = [&](int s, int bsel) {
        int k0 = s << 5;
        uint32_t bufb = sbase + bsel * BUF_B;
#pragma unroll
        for (int tile = 0; tile < 4; tile++) {
            const __nv_bfloat16* src = gsrc[tile];
            int r0 = ((tile < 2) ? bm : bn) << 7;
            uint32_t tb = bufb + tile * TILE_B;
#pragma unroll
            for (int i = 0; i < 2; i++) {
                int row = lrow + i * 64;
                const void* gp = src + (size_t)(r0 + row) * K + k0 + lc * 8;
                uint32_t dp = tb + row * TST + lc * 16;
                CP_ASYNC16(dp, gp);
            }
        }
    };

    load_stage(0, 0);
    CP_COMMIT();

    for (int s = 0; s < S; s++) {
        int b = s & 1;
        CP_WAIT0();
        __syncthreads();                        // buffer b ready; buffer b^1 free
        if (s + 1 < S) { load_stage(s + 1, b ^ 1); CP_COMMIT(); }

        uint32_t bufb = sbase + b * BUF_B;
        uint32_t aHb = bufb, aLb = bufb + TILE_B;
        uint32_t bHb = bufb + 2 * TILE_B, bLb = bufb + 3 * TILE_B;
#pragma unroll
        for (int ks = 0; ks < 2; ks++) {
            int cb = ks * 2;
            uint32_t bh[4][2], bl[4][2];
#pragma unroll
            for (int nfp = 0; nfp < 2; nfp++) {
                int nr = n_base + nfp * 16 + ((l >> 4) << 3) + (l & 7);
                int cc = cb + ((l >> 3) & 1);
                uint32_t addr = (uint32_t)(nr * TST + cc * 16);
                uint32_t r0, r1, r2, r3;
                LDSM4(r0, r1, r2, r3, bHb + addr);
                bh[nfp * 2][0] = r0; bh[nfp * 2][1] = r1;
                bh[nfp * 2 + 1][0] = r2; bh[nfp * 2 + 1][1] = r3;
                LDSM4(r0, r1, r2, r3, bLb + addr);
                bl[nfp * 2][0] = r0; bl[nfp * 2][1] = r1;
                bl[nfp * 2 + 1][0] = r2; bl[nfp * 2 + 1][1] = r3;
            }
#pragma unroll
            for (int mf = 0; mf < 4; mf++) {
                int mr = m_base + mf * 16 + (l & 15);
                int cc = cb + (l >> 4);
                uint32_t addr = (uint32_t)(mr * TST + cc * 16);
                uint32_t ah[4], al[4];
                LDSM4(ah[0], ah[1], ah[2], ah[3], aHb + addr);
                LDSM4(al[0], al[1], al[2], al[3], aLb + addr);
#pragma unroll
                for (int nf = 0; nf < 4; nf++) mma_bf16(acc[mf][nf], ah, bh[nf]);
#pragma unroll
                for (int nf = 0; nf < 4; nf++) mma_bf16(acc[mf][nf], ah, bl[nf]);
#pragma unroll
                for (int nf = 0; nf < 4; nf++) mma_bf16(acc[mf][nf], al, bh[nf]);
            }
        }
    }

    // ---- epilogue: direct stores from acc (mma C layout) ----
    int gid = l >> 2, tig = l & 3;
#pragma unroll
    for (int mf = 0; mf < 4; mf++) {
        int row0 = (bm << 7) + m_base + mf * 16 + gid;
#pragma unroll
        for (int nf = 0; nf < 4; nf++) {
            int col = (bn << 7) + n_base + nf * 8 + tig * 2;
            float bx = 0.f, by = 0.f;
            if (bias) { bx = bias[col]; by = bias[col + 1]; }
#pragma unroll
            for (int half = 0; half < 2; half++) {
                int row = row0 + half * 8;
                float vx = acc[mf][nf][half * 2 + 0] + bx;
                float vy = acc[mf][nf][half * 2 + 1] + by;
                size_t o = (size_t)row * N + col;
                if (Chi) {   // gelu -> split bf16
                    vx = 0.5f * vx * (1.0f + erff(vx * 0.70710678118654752f));
                    vy = 0.5f * vy * (1.0f + erff(vy * 0.70710678118654752f));
                    __nv_bfloat16 h0, l0, h1, l1;
                    fsplit(vx, h0, l0); fsplit(vy, h1, l1);
                    __nv_bfloat162 ph; ph.x = h0; ph.y = h1;
                    __nv_bfloat162 pl; pl.x = l0; pl.y = l1;
                    *(__nv_bfloat162*)(Chi + o) = ph;
                    *(__nv_bfloat162*)(Clo + o) = pl;
                } else {
                    if (res) {
                        float2 rr = *(const float2*)(res + o);
                        vx += rr.x; vy += rr.y;
                    }
                    float2 ov; ov.x = vx; ov.y = vy;
                    *(float2*)(Cf + o) = ov;
                }
            }
        }
    }
}

__global__ __launch_bounds__(256, 2) void gemm12_kernel(
    const __nv_bfloat16* ah, const __nv_bfloat16* al,
    const __nv_bfloat16* bh, const __nv_bfloat16* bl,
    const float* bias, const float* res,
    float* Cf, __nv_bfloat16* Chi, __nv_bfloat16* Clo, int N, int K) {
    extern __shared__ char smem[];
    gemm12_body(ah, al, bh, bl, bias, res, Cf, Chi, Clo, N, K, smem);
}

__global__ __launch_bounds__(256, 2) void gemm12_qkv_kernel(
    const __nv_bfloat16* ah, const __nv_bfloat16* al,
    const __nv_bfloat16* wqh, const __nv_bfloat16* wql,
    const __nv_bfloat16* wkh, const __nv_bfloat16* wkl,
    const __nv_bfloat16* wvh, const __nv_bfloat16* wvl,
    const float* bq, const float* bk, const float* bv,
    float* q, float* k, float* v) {
    extern __shared__ char smem[];
    const __nv_bfloat16 *bh, *bl; const float* bi; float* out;
    if (blockIdx.z == 0)      { bh = wqh; bl = wql; bi = bq; out = q; }
    else if (blockIdx.z == 1) { bh = wkh; bl = wkl; bi = bk; out = k; }
    else                      { bh = wvh; bl = wvl; bi = bv; out = v; }
    gemm12_body(ah, al, bh, bl, bi, nullptr, out, nullptr, nullptr, DD, DD, smem);
}

// ---------------- flash attention: block = (qtile64, h, b), 256 threads ----------------
#define FST 68
__global__ __launch_bounds__(256) void flash_attn_kernel(const float* __restrict__ Q,
                                                         const float* __restrict__ Kc,
                                                         const float* __restrict__ Vc,
                                                         __nv_bfloat16* __restrict__ Ohi,
                                                         __nv_bfloat16* __restrict__ Olo) {
    extern __shared__ float sb[];
    float* Qt = sb;
    float* Kt = Qt + 64 * FST;
    float* Vs = Kt + 64 * FST;
    float* Ps = Vs + 64 * FST;
    float* smx = Ps + 64 * FST;
    float* slx = smx + 64;
    float* sfx = slx + 64;

    int qt = blockIdx.x, h = blockIdx.y, b = blockIdx.z;
    int t = threadIdx.x;

    {
        int q = t & 63, d4 = t >> 6;
#pragma unroll
        for (int i = 0; i < 4; i++) {
            int dd4 = d4 + 4 * i;
            float4 f = *(const float4*)(Q + (size_t)(b * SS + qt * 64 + q) * DD + h * HD + dd4 * 4);
            Qt[(dd4 * 4 + 0) * FST + q] = f.x * 0.125f;
            Qt[(dd4 * 4 + 1) * FST + q] = f.y * 0.125f;
            Qt[(dd4 * 4 + 2) * FST + q] = f.z * 0.125f;
            Qt[(dd4 * 4 + 3) * FST + q] = f.w * 0.125f;
        }
    }
    if (t < 64) { smx[t] = -1e30f; slx[t] = 0.f; }

    float o[4][4];
#pragma unroll
    for (int i = 0; i < 4; i++)
#pragma unroll
        for (int j = 0; j < 4; j++) o[i][j] = 0.f;

    int qg = t & 15, kg = t >> 4;
    int qg2 = t >> 4, dg = t & 15;

    __syncthreads();

    for (int kt = 0; kt <= qt; kt++) {
        {
            int k = t & 63, d4 = t >> 6;
#pragma unroll
            for (int i = 0; i < 4; i++) {
                int dd4 = d4 + 4 * i;
                float4 f = *(const float4*)(Kc + (size_t)(b * SS + kt * 64 + k) * DD + h * HD + dd4 * 4);
                Kt[(dd4 * 4 + 0) * FST + k] = f.x;
                Kt[(dd4 * 4 + 1) * FST + k] = f.y;
                Kt[(dd4 * 4 + 2) * FST + k] = f.z;
                Kt[(dd4 * 4 + 3) * FST + k] = f.w;
            }
            int kv = t >> 4, dv4 = t & 15;
#pragma unroll
            for (int i = 0; i < 4; i++) {
                int kk = kv + 16 * i;
                float4 f = *(const float4*)(Vc + (size_t)(b * SS + kt * 64 + kk) * DD + h * HD + dv4 * 4);
                *(float4*)&Vs[kk * FST + dv4 * 4] = f;
            }
        }
        __syncthreads();

        float s[4][4];
#pragma unroll
        for (int i = 0; i < 4; i++)
#pragma unroll
            for (int j = 0; j < 4; j++) s[i][j] = 0.f;
        for (int d = 0; d < 64; d++) {
            float4 q4 = *(const float4*)&Qt[d * FST + qg * 4];
            float4 k4 = *(const float4*)&Kt[d * FST + kg * 4];
            float qa[4] = {q4.x, q4.y, q4.z, q4.w};
            float ka[4] = {k4.x, k4.y, k4.z, k4.w};
#pragma unroll
            for (int i = 0; i < 4; i++)
#pragma unroll
                for (int j = 0; j < 4; j++)
                    s[i][j] = fmaf(qa[i], ka[j], s[i][j]);
        }
        if (kt == qt) {
#pragma unroll
            for (int i = 0; i < 4; i++)
#pragma unroll
                for (int j = 0; j < 4; j++)
                    if (kg * 4 + j > qg * 4 + i) s[i][j] = -1e30f;
        }
#pragma unroll
        for (int j = 0; j < 4; j++)
#pragma unroll
            for (int i = 0; i < 4; i++)
                Ps[(kg * 4 + j) * FST + qg * 4 + i] = s[i][j];
        __syncthreads();

        if (t < 64) {
            int q = t;
            float m_old = smx[q];
            float tm = -1e30f;
            for (int k = 0; k < 64; k++) tm = fmaxf(tm, Ps[k * FST + q]);
            float mn = fmaxf(m_old, tm);
            float f = __expf(m_old - mn);
            float ssum = 0.f;
            for (int k = 0; k < 64; k++) {
                float pp = __expf(Ps[k * FST + q] - mn);
                Ps[k * FST + q] = pp;
                ssum += pp;
            }
            smx[q] = mn;
            slx[q] = slx[q] * f + ssum;
            sfx[q] = f;
        }
        __syncthreads();

        {
            float f0 = sfx[qg2 * 4 + 0], f1 = sfx[qg2 * 4 + 1];
            float f2 = sfx[qg2 * 4 + 2], f3 = sfx[qg2 * 4 + 3];
#pragma unroll
            for (int j = 0; j < 4; j++) {
                o[0][j] *= f0; o[1][j] *= f1; o[2][j] *= f2; o[3][j] *= f3;
            }
        }
        for (int k = 0; k < 64; k++) {
            float4 p4 = *(const float4*)&Ps[k * FST + qg2 * 4];
            float4 v4 = *(const float4*)&Vs[k * FST + dg * 4];
            float pa[4] = {p4.x, p4.y, p4.z, p4.w};
            float va[4] = {v4.x, v4.y, v4.z, v4.w};
#pragma unroll
            for (int i = 0; i < 4; i++)
#pragma unroll
                for (int j = 0; j < 4; j++)
                    o[i][j] = fmaf(pa[i], va[j], o[i][j]);
        }
        __syncthreads();
    }

#pragma unroll
    for (int i = 0; i < 4; i++) {
        int q = qg2 * 4 + i;
        float inv = 1.0f / slx[q];
        float v0 = o[i][0] * inv, v1 = o[i][1] * inv;
        float v2 = o[i][2] * inv, v3 = o[i][3] * inv;
        __nv_bfloat16 h0, l0, h1, l1, h2, l2, h3, l3;
        fsplit(v0, h0, l0); fsplit(v1, h1, l1);
        fsplit(v2, h2, l2); fsplit(v3, h3, l3);
        size_t idx = (size_t)(b * SS + qt * 64 + q) * DD + h * HD + dg * 4;
        __nv_bfloat162 ph0; ph0.x = h0; ph0.y = h1;
        __nv_bfloat162 ph1; ph1.x = h2; ph1.y = h3;
        __nv_bfloat162 pl0; pl0.x = l0; pl0.y = l1;
        __nv_bfloat162 pl1; pl1.x = l2; pl1.y = l3;
        *(__nv_bfloat162*)(Ohi + idx) = ph0;
        *(__nv_bfloat162*)(Ohi + idx + 2) = ph1;
        *(__nv_bfloat162*)(Olo + idx) = pl0;
        *(__nv_bfloat162*)(Olo + idx + 2) = pl1;
    }
}

// ---------------- launch ----------------
extern "C" void kernel_launch(void* const* d_in, const int* in_sizes, int n_in,
                              void* d_out, int out_size) {
    const float* emb  = (const float*)d_in[0];
    const float* Wq   = (const float*)d_in[1];
    const float* bq   = (const float*)d_in[2];
    const float* Wk   = (const float*)d_in[3];
    const float* bk   = (const float*)d_in[4];
    const float* Wv   = (const float*)d_in[5];
    const float* bv   = (const float*)d_in[6];
    const float* Wo   = (const float*)d_in[7];
    const float* bo   = (const float*)d_in[8];
    const float* ln1g = (const float*)d_in[9];
    const float* ln1b = (const float*)d_in[10];
    const float* W1   = (const float*)d_in[11];
    const float* b1   = (const float*)d_in[12];
    const float* W2   = (const float*)d_in[13];
    const float* b2   = (const float*)d_in[14];
    const float* ln2g = (const float*)d_in[15];
    const float* ln2b = (const float*)d_in[16];
    const float* lnfg = (const float*)d_in[17];
    const float* lnfb = (const float*)d_in[18];
    const float* Wout = (const float*)d_in[19];
    const int*   ids  = (const int*)d_in[20];

    __nv_bfloat16 *whi, *wlo, *hhi, *hlo, *athi, *atlo, *ffhi, *fflo;
    float *x, *q, *k, *v;
    cudaGetSymbolAddress((void**)&whi, g_whi);
    cudaGetSymbolAddress((void**)&wlo, g_wlo);
    cudaGetSymbolAddress((void**)&x,   g_x);
    cudaGetSymbolAddress((void**)&q,   g_q);
    cudaGetSymbolAddress((void**)&k,   g_k);
    cudaGetSymbolAddress((void**)&v,   g_v);
    cudaGetSymbolAddress((void**)&hhi, g_hhi);
    cudaGetSymbolAddress((void**)&hlo, g_hlo);
    cudaGetSymbolAddress((void**)&athi, g_athi);
    cudaGetSymbolAddress((void**)&atlo, g_atlo);
    cudaGetSymbolAddress((void**)&ffhi, g_ffhi);
    cudaGetSymbolAddress((void**)&fflo, g_fflo);

    static int attr_set = 0;
    const int flash_smem = (4 * 64 * FST + 3 * 64) * 4;
    if (!attr_set) {
        cudaFuncSetAttribute(flash_attn_kernel, cudaFuncAttributeMaxDynamicSharedMemorySize, flash_smem);
        cudaFuncSetAttribute(gemm12_kernel, cudaFuncAttributeMaxDynamicSharedMemorySize, GEMM_SMEM);
        cudaFuncSetAttribute(gemm12_qkv_kernel, cudaFuncAttributeMaxDynamicSharedMemorySize, GEMM_SMEM);
        attr_set = 1;
    }

    // ---- weight prep: transpose + split ----
    tsplit_kernel<<<dim3(DD / 32, DD / 32, LL), 256>>>(Wq, whi + OFF_WQ, wlo + OFF_WQ, DD, DD);
    tsplit_kernel<<<dim3(DD / 32, DD / 32, LL), 256>>>(Wk, whi + OFF_WK, wlo + OFF_WK, DD, DD);
    tsplit_kernel<<<dim3(DD / 32, DD / 32, LL), 256>>>(Wv, whi + OFF_WV, wlo + OFF_WV, DD, DD);
    tsplit_kernel<<<dim3(DD / 32, DD / 32, LL), 256>>>(Wo, whi + OFF_WO, wlo + OFF_WO, DD, DD);
    tsplit_kernel<<<dim3(FFD / 32, DD / 32, LL), 256>>>(W1, whi + OFF_W1, wlo + OFF_W1, DD, FFD);
    tsplit_kernel<<<dim3(DD / 32, FFD / 32, LL), 256>>>(W2, whi + OFF_W2, wlo + OFF_W2, FFD, DD);
    tsplit_kernel<<<dim3(VV / 32, DD / 32, 1), 256>>>(Wout, whi + OFF_WOUT, wlo + OFF_WOUT, DD, VV);

    embed_kernel<<<(TT * DD) / 256, 256>>>(emb, ids, x);

    dim3 gN1(DD / 128, TT / 128);        // (8, 16)
    dim3 gQKV(DD / 128, TT / 128, 3);    // (8, 16, 3)
    dim3 gFF1(FFD / 128, TT / 128);      // (32, 16)
    dim3 gOut(VV / 128, TT / 128);       // (250, 16)
    dim3 gAttn(SS / 64, HH, BB);         // (16, 16, 2)

    for (int l = 0; l < LL; l++) {
        size_t wo1 = (size_t)l * DD * DD;
        size_t woF = (size_t)l * DD * FFD;
        ln_kernel<<<TT, 256>>>(x, ln1g + l * DD, ln1b + l * DD, hhi, hlo);
        gemm12_qkv_kernel<<<gQKV, 256, GEMM_SMEM>>>(
            hhi, hlo,
            whi + OFF_WQ + wo1, wlo + OFF_WQ + wo1,
            whi + OFF_WK + wo1, wlo + OFF_WK + wo1,
            whi + OFF_WV + wo1, wlo + OFF_WV + wo1,
            bq + l * DD, bk + l * DD, bv + l * DD, q, k, v);
        flash_attn_kernel<<<gAttn, 256, flash_smem>>>(q, k, v, athi, atlo);
        gemm12_kernel<<<gN1, 256, GEMM_SMEM>>>(
            athi, atlo, whi + OFF_WO + wo1, wlo + OFF_WO + wo1,
            bo + l * DD, x, x, nullptr, nullptr, DD, DD);
        ln_kernel<<<TT, 256>>>(x, ln2g + l * DD, ln2b + l * DD, hhi, hlo);
        gemm12_kernel<<<gFF1, 256, GEMM_SMEM>>>(
            hhi, hlo, whi + OFF_W1 + woF, wlo + OFF_W1 + woF,
            b1 + l * FFD, nullptr, nullptr, ffhi, fflo, FFD, DD);
        gemm12_kernel<<<gN1, 256, GEMM_SMEM>>>(
            ffhi, fflo, whi + OFF_W2 + woF, wlo + OFF_W2 + woF,
            b2 + l * DD, x, x, nullptr, nullptr, DD, FFD);
    }
    ln_kernel<<<TT, 256>>>(x, lnfg, lnfb, hhi, hlo);
    gemm12_kernel<<<gOut, 256, GEMM_SMEM>>>(
        hhi, hlo, whi + OFF_WOUT, wlo + OFF_WOUT,
        nullptr, nullptr, (float*)d_out, nullptr, nullptr, VV, DD);
}

// round 13
// speedup vs baseline: 2.3727x; 1.0007x over previous
#include <cuda_runtime.h>
#include <cuda_bf16.h>
#include <math.h>
#include <stdint.h>

#define TT 2048      // B*S tokens
#define DD 1024      // model dim
#define FFD 4096     // ff dim
#define VV 32000     // vocab
#define HH 16        // heads
#define HD 64        // head dim
#define LL 6         // layers
#define SS 1024      // seq len
#define BB 2         // batch

// ---------------- weight scratch offsets (elements) ----------------
#define OFF_WQ   0ULL
#define OFF_WK   (OFF_WQ + 6ULL * 1024 * 1024)
#define OFF_WV   (OFF_WK + 6ULL * 1024 * 1024)
#define OFF_WO   (OFF_WV + 6ULL * 1024 * 1024)
#define OFF_W1   (OFF_WO + 6ULL * 1024 * 1024)
#define OFF_W2   (OFF_W1 + 6ULL * 1024 * 4096)
#define OFF_WOUT (OFF_W2 + 6ULL * 4096 * 1024)
#define W_TOTAL  (OFF_WOUT + 1024ULL * 32000)

// ---------------- scratch (no allocation allowed) ----------------
__device__ __nv_bfloat16 g_whi[W_TOTAL];
__device__ __nv_bfloat16 g_wlo[W_TOTAL];
__device__ float g_x[TT * DD];
__device__ float g_q[TT * DD];
__device__ float g_k[TT * DD];
__device__ float g_v[TT * DD];
__device__ __nv_bfloat16 g_hhi[TT * DD];
__device__ __nv_bfloat16 g_hlo[TT * DD];
__device__ __nv_bfloat16 g_athi[TT * DD];
__device__ __nv_bfloat16 g_atlo[TT * DD];
__device__ __nv_bfloat16 g_ffhi[TT * FFD];
__device__ __nv_bfloat16 g_fflo[TT * FFD];

// ---------------- baseline-PTX helpers ----------------
__device__ __forceinline__ uint32_t smem_u32(const void* p) {
    uint32_t a;
    asm("{ .reg .u64 t; cvta.to.shared.u64 t, %1; cvt.u32.u64 %0, t; }" : "=r"(a) : "l"(p));
    return a;
}
#define CP_ASYNC16(dst, src) \
    asm volatile("cp.async.cg.shared.global [%0], [%1], 16;" :: "r"(dst), "l"(src))
#define CP_COMMIT() asm volatile("cp.async.commit_group;" ::: "memory")
#define CP_WAIT0()  asm volatile("cp.async.wait_group 0;" ::: "memory")
#define LDSM4(r0, r1, r2, r3, a) \
    asm volatile("ldmatrix.sync.aligned.m8n8.x4.shared.b16 {%0,%1,%2,%3}, [%4];" \
                 : "=r"(r0), "=r"(r1), "=r"(r2), "=r"(r3) : "r"(a))

__device__ __forceinline__ void mma_bf16(float* c, const uint32_t* a, const uint32_t* b) {
    asm volatile(
        "mma.sync.aligned.m16n8k16.row.col.f32.bf16.bf16.f32 "
        "{%0,%1,%2,%3}, {%4,%5,%6,%7}, {%8,%9}, {%0,%1,%2,%3};\n"
        : "+f"(c[0]), "+f"(c[1]), "+f"(c[2]), "+f"(c[3])
        : "r"(a[0]), "r"(a[1]), "r"(a[2]), "r"(a[3]), "r"(b[0]), "r"(b[1]));
}

__device__ __forceinline__ void fsplit(float v, __nv_bfloat16& h, __nv_bfloat16& l) {
    h = __float2bfloat16(v);
    l = __float2bfloat16(v - __bfloat162float(h));
}

// ---------------- weight transpose+split: [K,N] fp32 -> [N,K] bf16 hi/lo ----------------
__global__ __launch_bounds__(256) void tsplit_kernel(const float* __restrict__ src,
                                                     __nv_bfloat16* __restrict__ dhi,
                                                     __nv_bfloat16* __restrict__ dlo,
                                                     int K, int N) {
    __shared__ float s[32][33];
    size_t zo = (size_t)blockIdx.z * K * N;
    src += zo; dhi += zo; dlo += zo;
    int n0 = blockIdx.x * 32, k0 = blockIdx.y * 32;
    int tx = threadIdx.x & 31, ty = threadIdx.x >> 5;
#pragma unroll
    for (int i = 0; i < 4; i++)
        s[ty + 8 * i][tx] = src[(size_t)(k0 + ty + 8 * i) * N + n0 + tx];
    __syncthreads();
#pragma unroll
    for (int i = 0; i < 4; i++) {
        int n = n0 + ty + 8 * i, k = k0 + tx;
        float v = s[tx][ty + 8 * i];
        __nv_bfloat16 h, l;
        fsplit(v, h, l);
        dhi[(size_t)n * K + k] = h;
        dlo[(size_t)n * K + k] = l;
    }
}

// ---------------- embedding + positional encoding ----------------
__global__ void embed_kernel(const float* __restrict__ emb,
                             const int* __restrict__ ids,
                             float* __restrict__ x) {
    int idx = blockIdx.x * 256 + threadIdx.x;
    if (idx >= TT * DD) return;
    int t = idx >> 10;
    int d = idx & (DD - 1);
    int pos = t & (SS - 1);
    float val = emb[ids[t] * DD + d] * 32.0f;
    float ang = (float)pos * expf((float)(d & ~1) * (-9.210340371976184f / 1024.0f));
    val += (d & 1) ? cosf(ang) : sinf(ang);
    x[idx] = val;
}

// ---------------- layernorm -> split bf16 output ----------------
__global__ __launch_bounds__(256) void ln_kernel(const float* __restrict__ x,
                                                 const float* __restrict__ g,
                                                 const float* __restrict__ bta,
                                                 __nv_bfloat16* __restrict__ ohi,
                                                 __nv_bfloat16* __restrict__ olo) {
    int row = blockIdx.x;
    const float* xr = x + (size_t)row * DD;
    float s1 = 0.f, s2 = 0.f;
    for (int i = threadIdx.x; i < DD; i += 256) {
        float v = xr[i];
        s1 += v;
        s2 = fmaf(v, v, s2);
    }
    for (int o = 16; o; o >>= 1) {
        s1 += __shfl_xor_sync(0xffffffffu, s1, o);
        s2 += __shfl_xor_sync(0xffffffffu, s2, o);
    }
    __shared__ float r1[8], r2[8];
    __shared__ float smean, srstd;
    int w = threadIdx.x >> 5, lane = threadIdx.x & 31;
    if (lane == 0) { r1[w] = s1; r2[w] = s2; }
    __syncthreads();
    if (threadIdx.x == 0) {
        float t1 = 0.f, t2 = 0.f;
        for (int i = 0; i < 8; i++) { t1 += r1[i]; t2 += r2[i]; }
        float mean = t1 * (1.0f / DD);
        float var  = t2 * (1.0f / DD) - mean * mean;
        smean = mean;
        srstd = rsqrtf(var + 1e-5f);
    }
    __syncthreads();
    float mean = smean, rstd = srstd;
    for (int i = threadIdx.x; i < DD; i += 256) {
        float v = (xr[i] - mean) * rstd * g[i] + bta[i];
        __nv_bfloat16 h, l;
        fsplit(v, h, l);
        ohi[(size_t)row * DD + i] = h;
        olo[(size_t)row * DD + i] = l;
    }
}

// ---------------- bf16x3 mma.sync GEMM with cp.async + ldmatrix ----------------
#define TST 80
#define TILE_B (128 * TST)
#define BUF_B (4 * TILE_B)
#define GEMM_SMEM (2 * BUF_B)

__device__ __forceinline__ void gemm12_body(
    const __nv_bfloat16* __restrict__ Ahg, const __nv_bfloat16* __restrict__ Alg,
    const __nv_bfloat16* __restrict__ Bhg, const __nv_bfloat16* __restrict__ Blg,
    const float* __restrict__ bias, const float* __restrict__ res,
    float* __restrict__ Cf, __nv_bfloat16* __restrict__ Chi, __nv_bfloat16* __restrict__ Clo,
    int N, int K, int bm, int bn, char* smem)
{
    uint32_t sbase = smem_u32(smem);
    int t = threadIdx.x, w = t >> 5, l = t & 31;
    int wm = w >> 2, wn = w & 3;
    int m_base = wm * 64, n_base = wn * 32;

    int lrow = w * 8 + (l & 7);
    int lc = l >> 3;
    const __nv_bfloat16* gsrc[4] = {Ahg, Alg, Bhg, Blg};

    float acc[4][4][4];
#pragma unroll
    for (int mf = 0; mf < 4; mf++)
#pragma unroll
        for (int nf = 0; nf < 4; nf++)
#pragma unroll
            for (int r = 0; r < 4; r++) acc[mf][nf][r] = 0.f;

    int S = K >> 5;

    auto load_stage = [&](int s, int bsel) {
        int k0 = s << 5;
        uint32_t bufb = sbase + bsel * BUF_B;
#pragma unroll
        for (int tile = 0; tile < 4; tile++) {
            const __nv_bfloat16* src = gsrc[tile];
            int r0 = ((tile < 2) ? bm : bn) << 7;
            uint32_t tb = bufb + tile * TILE_B;
#pragma unroll
            for (int i = 0; i < 2; i++) {
                int row = lrow + i * 64;
                const void* gp = src + (size_t)(r0 + row) * K + k0 + lc * 8;
                uint32_t dp = tb + row * TST + lc * 16;
                CP_ASYNC16(dp, gp);
            }
        }
    };

    load_stage(0, 0);
    CP_COMMIT();

    for (int s = 0; s < S; s++) {
        int b = s & 1;
        CP_WAIT0();
        __syncthreads();
        if (s + 1 < S) { load_stage(s + 1, b ^ 1); CP_COMMIT(); }

        uint32_t bufb = sbase + b * BUF_B;
        uint32_t aHb = bufb, aLb = bufb + TILE_B;
        uint32_t bHb = bufb + 2 * TILE_B, bLb = bufb + 3 * TILE_B;
#pragma unroll
        for (int ks = 0; ks < 2; ks++) {
            int cb = ks * 2;
            uint32_t bh[4][2], bl[4][2];
#pragma unroll
            for (int nfp = 0; nfp < 2; nfp++) {
                int nr = n_base + nfp * 16 + ((l >> 4) << 3) + (l & 7);
                int cc = cb + ((l >> 3) & 1);
                uint32_t addr = (uint32_t)(nr * TST + cc * 16);
                uint32_t r0, r1, r2, r3;
                LDSM4(r0, r1, r2, r3, bHb + addr);
                bh[nfp * 2][0] = r0; bh[nfp * 2][1] = r1;
                bh[nfp * 2 + 1][0] = r2; bh[nfp * 2 + 1][1] = r3;
                LDSM4(r0, r1, r2, r3, bLb + addr);
                bl[nfp * 2][0] = r0; bl[nfp * 2][1] = r1;
                bl[nfp * 2 + 1][0] = r2; bl[nfp * 2 + 1][1] = r3;
            }
#pragma unroll
            for (int mf = 0; mf < 4; mf++) {
                int mr = m_base + mf * 16 + (l & 15);
                int cc = cb + (l >> 4);
                uint32_t addr = (uint32_t)(mr * TST + cc * 16);
                uint32_t ah[4], al[4];
                LDSM4(ah[0], ah[1], ah[2], ah[3], aHb + addr);
                LDSM4(al[0], al[1], al[2], al[3], aLb + addr);
#pragma unroll
                for (int nf = 0; nf < 4; nf++) mma_bf16(acc[mf][nf], ah, bh[nf]);
#pragma unroll
                for (int nf = 0; nf < 4; nf++) mma_bf16(acc[mf][nf], ah, bl[nf]);
#pragma unroll
                for (int nf = 0; nf < 4; nf++) mma_bf16(acc[mf][nf], al, bh[nf]);
            }
        }
    }

    int gid = l >> 2, tig = l & 3;
#pragma unroll
    for (int mf = 0; mf < 4; mf++) {
        int row0 = (bm << 7) + m_base + mf * 16 + gid;
#pragma unroll
        for (int nf = 0; nf < 4; nf++) {
            int col = (bn << 7) + n_base + nf * 8 + tig * 2;
            float bx = 0.f, by = 0.f;
            if (bias) { bx = bias[col]; by = bias[col + 1]; }
#pragma unroll
            for (int half = 0; half < 2; half++) {
                int row = row0 + half * 8;
                float vx = acc[mf][nf][half * 2 + 0] + bx;
                float vy = acc[mf][nf][half * 2 + 1] + by;
                size_t o = (size_t)row * N + col;
                if (Chi) {
                    vx = 0.5f * vx * (1.0f + erff(vx * 0.70710678118654752f));
                    vy = 0.5f * vy * (1.0f + erff(vy * 0.70710678118654752f));
                    __nv_bfloat16 h0, l0, h1, l1;
                    fsplit(vx, h0, l0); fsplit(vy, h1, l1);
                    __nv_bfloat162 ph; ph.x = h0; ph.y = h1;
                    __nv_bfloat162 pl; pl.x = l0; pl.y = l1;
                    *(__nv_bfloat162*)(Chi + o) = ph;
                    *(__nv_bfloat162*)(Clo + o) = pl;
                } else {
                    if (res) {
                        float2 rr = *(const float2*)(res + o);
                        vx += rr.x; vy += rr.y;
                    }
                    float2 ov; ov.x = vx; ov.y = vy;
                    *(float2*)(Cf + o) = ov;
                }
            }
        }
    }
}

// swap!=0: bm on blockIdx.x (fast axis) so B-tile sharers are co-scheduled (logits GEMM)
__global__ __launch_bounds__(256, 2) void gemm12_kernel(
    const __nv_bfloat16* ah, const __nv_bfloat16* al,
    const __nv_bfloat16* bh, const __nv_bfloat16* bl,
    const float* bias, const float* res,
    float* Cf, __nv_bfloat16* Chi, __nv_bfloat16* Clo, int N, int K, int swap) {
    extern __shared__ char smem[];
    int bm = swap ? blockIdx.x : blockIdx.y;
    int bn = swap ? blockIdx.y : blockIdx.x;
    gemm12_body(ah, al, bh, bl, bias, res, Cf, Chi, Clo, N, K, bm, bn, smem);
}

__global__ __launch_bounds__(256, 2) void gemm12_qkv_kernel(
    const __nv_bfloat16* ah, const __nv_bfloat16* al,
    const __nv_bfloat16* wqh, const __nv_bfloat16* wql,
    const __nv_bfloat16* wkh, const __nv_bfloat16* wkl,
    const __nv_bfloat16* wvh, const __nv_bfloat16* wvl,
    const float* bq, const float* bk, const float* bv,
    float* q, float* k, float* v) {
    extern __shared__ char smem[];
    const __nv_bfloat16 *bh, *bl; const float* bi; float* out;
    if (blockIdx.z == 0)      { bh = wqh; bl = wql; bi = bq; out = q; }
    else if (blockIdx.z == 1) { bh = wkh; bl = wkl; bi = bk; out = k; }
    else                      { bh = wvh; bl = wvl; bi = bv; out = v; }
    gemm12_body(ah, al, bh, bl, bi, nullptr, out, nullptr, nullptr, DD, DD,
                blockIdx.y, blockIdx.x, smem);
}

// ---------------- flash attention: block = (qtile64, h, b), 256 threads ----------------
// parallel online softmax: 4 segments x 64 q, two-level reduce via smem
#define FST 68
#define FLASH_SMEM ((4 * 64 * FST + 3 * 64 + 2 * 256) * 4)
__global__ __launch_bounds__(256) void flash_attn_kernel(const float* __restrict__ Q,
                                                         const float* __restrict__ Kc,
                                                         const float* __restrict__ Vc,
                                                         __nv_bfloat16* __restrict__ Ohi,
                                                         __nv_bfloat16* __restrict__ Olo) {
    extern __shared__ float sb[];
    float* Qt = sb;
    float* Kt = Qt + 64 * FST;
    float* Vs = Kt + 64 * FST;
    float* Ps = Vs + 64 * FST;
    float* smx = Ps + 64 * FST;
    float* slx = smx + 64;
    float* sfx = slx + 64;
    float* pmS = sfx + 64;      // [4][64] partial max
    float* psS = pmS + 256;     // [4][64] partial sum

    int qt = blockIdx.x, h = blockIdx.y, b = blockIdx.z;
    int t = threadIdx.x;

    {
        int q = t & 63, d4 = t >> 6;
#pragma unroll
        for (int i = 0; i < 4; i++) {
            int dd4 = d4 + 4 * i;
            float4 f = *(const float4*)(Q + (size_t)(b * SS + qt * 64 + q) * DD + h * HD + dd4 * 4);
            Qt[(dd4 * 4 + 0) * FST + q] = f.x * 0.125f;
            Qt[(dd4 * 4 + 1) * FST + q] = f.y * 0.125f;
            Qt[(dd4 * 4 + 2) * FST + q] = f.z * 0.125f;
            Qt[(dd4 * 4 + 3) * FST + q] = f.w * 0.125f;
        }
    }
    if (t < 64) { smx[t] = -1e30f; slx[t] = 0.f; }

    float o[4][4];
#pragma unroll
    for (int i = 0; i < 4; i++)
#pragma unroll
        for (int j = 0; j < 4; j++) o[i][j] = 0.f;

    int qg = t & 15, kg = t >> 4;
    int qg2 = t >> 4, dg = t & 15;
    int sq = t & 63, seg = t >> 6;      // softmax mapping

    __syncthreads();

    for (int kt = 0; kt <= qt; kt++) {
        {
            int k = t & 63, d4 = t >> 6;
#pragma unroll
            for (int i = 0; i < 4; i++) {
                int dd4 = d4 + 4 * i;
                float4 f = *(const float4*)(Kc + (size_t)(b * SS + kt * 64 + k) * DD + h * HD + dd4 * 4);
                Kt[(dd4 * 4 + 0) * FST + k] = f.x;
                Kt[(dd4 * 4 + 1) * FST + k] = f.y;
                Kt[(dd4 * 4 + 2) * FST + k] = f.z;
                Kt[(dd4 * 4 + 3) * FST + k] = f.w;
            }
            int kv = t >> 4, dv4 = t & 15;
#pragma unroll
            for (int i = 0; i < 4; i++) {
                int kk = kv + 16 * i;
                float4 f = *(const float4*)(Vc + (size_t)(b * SS + kt * 64 + kk) * DD + h * HD + dv4 * 4);
                *(float4*)&Vs[kk * FST + dv4 * 4] = f;
            }
        }
        __syncthreads();

        float s[4][4];
#pragma unroll
        for (int i = 0; i < 4; i++)
#pragma unroll
            for (int j = 0; j < 4; j++) s[i][j] = 0.f;
        for (int d = 0; d < 64; d++) {
            float4 q4 = *(const float4*)&Qt[d * FST + qg * 4];
            float4 k4 = *(const float4*)&Kt[d * FST + kg * 4];
            float qa[4] = {q4.x, q4.y, q4.z, q4.w};
            float ka[4] = {k4.x, k4.y, k4.z, k4.w};
#pragma unroll
            for (int i = 0; i < 4; i++)
#pragma unroll
                for (int j = 0; j < 4; j++)
                    s[i][j] = fmaf(qa[i], ka[j], s[i][j]);
        }
        if (kt == qt) {
#pragma unroll
            for (int i = 0; i < 4; i++)
#pragma unroll
                for (int j = 0; j < 4; j++)
                    if (kg * 4 + j > qg * 4 + i) s[i][j] = -1e30f;
        }
#pragma unroll
        for (int j = 0; j < 4; j++)
#pragma unroll
            for (int i = 0; i < 4; i++)
                Ps[(kg * 4 + j) * FST + qg * 4 + i] = s[i][j];
        __syncthreads();

        // ---- parallel online softmax ----
        {   // phase 1: per-segment max over 16 k's
            float pm = -1e30f;
            int k0 = seg * 16;
#pragma unroll
            for (int k = 0; k < 16; k++) pm = fmaxf(pm, Ps[(k0 + k) * FST + sq]);
            pmS[seg * 64 + sq] = pm;
        }
        __syncthreads();
        {   // phase 2: full max, exp + partial sum
            float m_old = smx[sq];
            float mn = fmaxf(fmaxf(pmS[sq], pmS[64 + sq]),
                             fmaxf(pmS[128 + sq], pmS[192 + sq]));
            mn = fmaxf(mn, m_old);
            float ssum = 0.f;
            int k0 = seg * 16;
#pragma unroll
            for (int k = 0; k < 16; k++) {
                float pp = __expf(Ps[(k0 + k) * FST + sq] - mn);
                Ps[(k0 + k) * FST + sq] = pp;
                ssum += pp;
            }
            psS[seg * 64 + sq] = ssum;
        }
        __syncthreads();
        if (t < 64) {   // phase 3: finalize running stats
            int q = t;
            float m_old = smx[q];
            float mn = fmaxf(fmaxf(pmS[q], pmS[64 + q]),
                             fmaxf(pmS[128 + q], pmS[192 + q]));
            mn = fmaxf(mn, m_old);
            float f = __expf(m_old - mn);
            slx[q] = slx[q] * f + (psS[q] + psS[64 + q] + psS[128 + q] + psS[192 + q]);
            smx[q] = mn;
            sfx[q] = f;
        }
        __syncthreads();

        {
            float f0 = sfx[qg2 * 4 + 0], f1 = sfx[qg2 * 4 + 1];
            float f2 = sfx[qg2 * 4 + 2], f3 = sfx[qg2 * 4 + 3];
#pragma unroll
            for (int j = 0; j < 4; j++) {
                o[0][j] *= f0; o[1][j] *= f1; o[2][j] *= f2; o[3][j] *= f3;
            }
        }
        for (int k = 0; k < 64; k++) {
            float4 p4 = *(const float4*)&Ps[k * FST + qg2 * 4];
            float4 v4 = *(const float4*)&Vs[k * FST + dg * 4];
            float pa[4] = {p4.x, p4.y, p4.z, p4.w};
            float va[4] = {v4.x, v4.y, v4.z, v4.w};
#pragma unroll
            for (int i = 0; i < 4; i++)
#pragma unroll
                for (int j = 0; j < 4; j++)
                    o[i][j] = fmaf(pa[i], va[j], o[i][j]);
        }
        __syncthreads();
    }

#pragma unroll
    for (int i = 0; i < 4; i++) {
        int q = qg2 * 4 + i;
        float inv = 1.0f / slx[q];
        float v0 = o[i][0] * inv, v1 = o[i][1] * inv;
        float v2 = o[i][2] * inv, v3 = o[i][3] * inv;
        __nv_bfloat16 h0, l0, h1, l1, h2, l2, h3, l3;
        fsplit(v0, h0, l0); fsplit(v1, h1, l1);
        fsplit(v2, h2, l2); fsplit(v3, h3, l3);
        size_t idx = (size_t)(b * SS + qt * 64 + q) * DD + h * HD + dg * 4;
        __nv_bfloat162 ph0; ph0.x = h0; ph0.y = h1;
        __nv_bfloat162 ph1; ph1.x = h2; ph1.y = h3;
        __nv_bfloat162 pl0; pl0.x = l0; pl0.y = l1;
        __nv_bfloat162 pl1; pl1.x = l2; pl1.y = l3;
        *(__nv_bfloat162*)(Ohi + idx) = ph0;
        *(__nv_bfloat162*)(Ohi + idx + 2) = ph1;
        *(__nv_bfloat162*)(Olo + idx) = pl0;
        *(__nv_bfloat162*)(Olo + idx + 2) = pl1;
    }
}

// ---------------- launch ----------------
extern "C" void kernel_launch(void* const* d_in, const int* in_sizes, int n_in,
                              void* d_out, int out_size) {
    const float* emb  = (const float*)d_in[0];
    const float* Wq   = (const float*)d_in[1];
    const float* bq   = (const float*)d_in[2];
    const float* Wk   = (const float*)d_in[3];
    const float* bk   = (const float*)d_in[4];
    const float* Wv   = (const float*)d_in[5];
    const float* bv   = (const float*)d_in[6];
    const float* Wo   = (const float*)d_in[7];
    const float* bo   = (const float*)d_in[8];
    const float* ln1g = (const float*)d_in[9];
    const float* ln1b = (const float*)d_in[10];
    const float* W1   = (const float*)d_in[11];
    const float* b1   = (const float*)d_in[12];
    const float* W2   = (const float*)d_in[13];
    const float* b2   = (const float*)d_in[14];
    const float* ln2g = (const float*)d_in[15];
    const float* ln2b = (const float*)d_in[16];
    const float* lnfg = (const float*)d_in[17];
    const float* lnfb = (const float*)d_in[18];
    const float* Wout = (const float*)d_in[19];
    const int*   ids  = (const int*)d_in[20];

    __nv_bfloat16 *whi, *wlo, *hhi, *hlo, *athi, *atlo, *ffhi, *fflo;
    float *x, *q, *k, *v;
    cudaGetSymbolAddress((void**)&whi, g_whi);
    cudaGetSymbolAddress((void**)&wlo, g_wlo);
    cudaGetSymbolAddress((void**)&x,   g_x);
    cudaGetSymbolAddress((void**)&q,   g_q);
    cudaGetSymbolAddress((void**)&k,   g_k);
    cudaGetSymbolAddress((void**)&v,   g_v);
    cudaGetSymbolAddress((void**)&hhi, g_hhi);
    cudaGetSymbolAddress((void**)&hlo, g_hlo);
    cudaGetSymbolAddress((void**)&athi, g_athi);
    cudaGetSymbolAddress((void**)&atlo, g_atlo);
    cudaGetSymbolAddress((void**)&ffhi, g_ffhi);
    cudaGetSymbolAddress((void**)&fflo, g_fflo);

    static int attr_set = 0;
    if (!attr_set) {
        cudaFuncSetAttribute(flash_attn_kernel, cudaFuncAttributeMaxDynamicSharedMemorySize, FLASH_SMEM);
        cudaFuncSetAttribute(gemm12_kernel, cudaFuncAttributeMaxDynamicSharedMemorySize, GEMM_SMEM);
        cudaFuncSetAttribute(gemm12_qkv_kernel, cudaFuncAttributeMaxDynamicSharedMemorySize, GEMM_SMEM);
        attr_set = 1;
    }

    // ---- weight prep: transpose + split ----
    tsplit_kernel<<<dim3(DD / 32, DD / 32, LL), 256>>>(Wq, whi + OFF_WQ, wlo + OFF_WQ, DD, DD);
    tsplit_kernel<<<dim3(DD / 32, DD / 32, LL), 256>>>(Wk, whi + OFF_WK, wlo + OFF_WK, DD, DD);
    tsplit_kernel<<<dim3(DD / 32, DD / 32, LL), 256>>>(Wv, whi + OFF_WV, wlo + OFF_WV, DD, DD);
    tsplit_kernel<<<dim3(DD / 32, DD / 32, LL), 256>>>(Wo, whi + OFF_WO, wlo + OFF_WO, DD, DD);
    tsplit_kernel<<<dim3(FFD / 32, DD / 32, LL), 256>>>(W1, whi + OFF_W1, wlo + OFF_W1, DD, FFD);
    tsplit_kernel<<<dim3(DD / 32, FFD / 32, LL), 256>>>(W2, whi + OFF_W2, wlo + OFF_W2, FFD, DD);
    tsplit_kernel<<<dim3(VV / 32, DD / 32, 1), 256>>>(Wout, whi + OFF_WOUT, wlo + OFF_WOUT, DD, VV);

    embed_kernel<<<(TT * DD) / 256, 256>>>(emb, ids, x);

    dim3 gN1(DD / 128, TT / 128);        // (8, 16)
    dim3 gQKV(DD / 128, TT / 128, 3);    // (8, 16, 3)
    dim3 gFF1(FFD / 128, TT / 128);      // (32, 16)
    dim3 gOut(TT / 128, VV / 128);       // (16, 250)  bm fast -> B-tile sharers co-run
    dim3 gAttn(SS / 64, HH, BB);         // (16, 16, 2)

    for (int l = 0; l < LL; l++) {
        size_t wo1 = (size_t)l * DD * DD;
        size_t woF = (size_t)l * DD * FFD;
        ln_kernel<<<TT, 256>>>(x, ln1g + l * DD, ln1b + l * DD, hhi, hlo);
        gemm12_qkv_kernel<<<gQKV, 256, GEMM_SMEM>>>(
            hhi, hlo,
            whi + OFF_WQ + wo1, wlo + OFF_WQ + wo1,
            whi + OFF_WK + wo1, wlo + OFF_WK + wo1,
            whi + OFF_WV + wo1, wlo + OFF_WV + wo1,
            bq + l * DD, bk + l * DD, bv + l * DD, q, k, v);
        flash_attn_kernel<<<gAttn, 256, FLASH_SMEM>>>(q, k, v, athi, atlo);
        gemm12_kernel<<<gN1, 256, GEMM_SMEM>>>(
            athi, atlo, whi + OFF_WO + wo1, wlo + OFF_WO + wo1,
            bo + l * DD, x, x, nullptr, nullptr, DD, DD, 0);
        ln_kernel<<<TT, 256>>>(x, ln2g + l * DD, ln2b + l * DD, hhi, hlo);
        gemm12_kernel<<<gFF1, 256, GEMM_SMEM>>>(
            hhi, hlo, whi + OFF_W1 + woF, wlo + OFF_W1 + woF,
            b1 + l * FFD, nullptr, nullptr, ffhi, fflo, FFD, DD, 0);
        gemm12_kernel<<<gN1, 256, GEMM_SMEM>>>(
            ffhi, fflo, whi + OFF_W2 + woF, wlo + OFF_W2 + woF,
            b2 + l * DD, x, x, nullptr, nullptr, DD, FFD, 0);
    }
    ln_kernel<<<TT, 256>>>(x, lnfg, lnfb, hhi, hlo);
    gemm12_kernel<<<gOut, 256, GEMM_SMEM>>>(
        hhi, hlo, whi + OFF_WOUT, wlo + OFF_WOUT,
        nullptr, nullptr, (float*)d_out, nullptr, nullptr, VV, DD, 1);
}

// round 15
// speedup vs baseline: 2.8161x; 1.1869x over previous
#include <cuda_runtime.h>
#include <cuda_bf16.h>
#include <math.h>
#include <stdint.h>

#define TT 2048      // B*S tokens
#define DD 1024      // model dim
#define FFD 4096     // ff dim
#define VV 32000     // vocab
#define HH 16        // heads
#define HD 64        // head dim
#define LL 6         // layers
#define SS 1024      // seq len
#define BB 2         // batch

// ---------------- weight scratch offsets (elements) ----------------
#define OFF_WQ   0ULL
#define OFF_WK   (OFF_WQ + 6ULL * 1024 * 1024)
#define OFF_WV   (OFF_WK + 6ULL * 1024 * 1024)
#define OFF_WO   (OFF_WV + 6ULL * 1024 * 1024)
#define OFF_W1   (OFF_WO + 6ULL * 1024 * 1024)
#define OFF_W2   (OFF_W1 + 6ULL * 1024 * 4096)
#define OFF_WOUT (OFF_W2 + 6ULL * 4096 * 1024)
#define W_TOTAL  (OFF_WOUT + 1024ULL * 32000)

// ---------------- scratch (no allocation allowed) ----------------
__device__ __nv_bfloat16 g_whi[W_TOTAL];
__device__ __nv_bfloat16 g_wlo[W_TOTAL];
__device__ float g_x[TT * DD];
__device__ __nv_bfloat16 g_qhi[TT * DD];
__device__ __nv_bfloat16 g_qlo[TT * DD];
__device__ __nv_bfloat16 g_khi[TT * DD];
__device__ __nv_bfloat16 g_klo[TT * DD];
__device__ __nv_bfloat16 g_vhi[TT * DD];
__device__ __nv_bfloat16 g_vlo[TT * DD];
__device__ __nv_bfloat16 g_hhi[TT * DD];
__device__ __nv_bfloat16 g_hlo[TT * DD];
__device__ __nv_bfloat16 g_athi[TT * DD];
__device__ __nv_bfloat16 g_atlo[TT * DD];
__device__ __nv_bfloat16 g_ffhi[TT * FFD];
__device__ __nv_bfloat16 g_fflo[TT * FFD];

// ---------------- baseline-PTX helpers ----------------
__device__ __forceinline__ uint32_t smem_u32(const void* p) {
    uint32_t a;
    asm("{ .reg .u64 t; cvta.to.shared.u64 t, %1; cvt.u32.u64 %0, t; }" : "=r"(a) : "l"(p));
    return a;
}
#define CP_ASYNC16(dst, src) \
    asm volatile("cp.async.cg.shared.global [%0], [%1], 16;" :: "r"(dst), "l"(src))
#define CP_COMMIT() asm volatile("cp.async.commit_group;" ::: "memory")
#define CP_WAIT0()  asm volatile("cp.async.wait_group 0;" ::: "memory")
#define LDSM4(r0, r1, r2, r3, a) \
    asm volatile("ldmatrix.sync.aligned.m8n8.x4.shared.b16 {%0,%1,%2,%3}, [%4];" \
                 : "=r"(r0), "=r"(r1), "=r"(r2), "=r"(r3) : "r"(a))
#define LDSM4T(r0, r1, r2, r3, a) \
    asm volatile("ldmatrix.sync.aligned.m8n8.x4.trans.shared.b16 {%0,%1,%2,%3}, [%4];" \
                 : "=r"(r0), "=r"(r1), "=r"(r2), "=r"(r3) : "r"(a))

__device__ __forceinline__ void mma_bf16(float* c, const uint32_t* a, const uint32_t* b) {
    asm volatile(
        "mma.sync.aligned.m16n8k16.row.col.f32.bf16.bf16.f32 "
        "{%0,%1,%2,%3}, {%4,%5,%6,%7}, {%8,%9}, {%0,%1,%2,%3};\n"
        : "+f"(c[0]), "+f"(c[1]), "+f"(c[2]), "+f"(c[3])
        : "r"(a[0]), "r"(a[1]), "r"(a[2]), "r"(a[3]), "r"(b[0]), "r"(b[1]));
}

__device__ __forceinline__ void fsplit(float v, __nv_bfloat16& h, __nv_bfloat16& l) {
    h = __float2bfloat16(v);
    l = __float2bfloat16(v - __bfloat162float(h));
}
// pack (f0 low, f1 high) into hi/lo bf16x2 words
__device__ __forceinline__ void split_bf16x2(float f0, float f1,
                                             uint32_t& hi, uint32_t& lo) {
    uint32_t h;
    asm("cvt.rn.bf16x2.f32 %0, %1, %2;" : "=r"(h) : "f"(f1), "f"(f0));
    float h0 = __uint_as_float(h << 16);
    float h1 = __uint_as_float(h & 0xffff0000u);
    float l0 = f0 - h0;
    float l1 = f1 - h1;
    uint32_t l;
    asm("cvt.rn.bf16x2.f32 %0, %1, %2;" : "=r"(l) : "f"(l1), "f"(l0));
    hi = h; lo = l;
}

// ---------------- weight transpose+split: [K,N] fp32 -> [N,K] bf16 hi/lo ----------------
__global__ __launch_bounds__(256) void tsplit_kernel(const float* __restrict__ src,
                                                     __nv_bfloat16* __restrict__ dhi,
                                                     __nv_bfloat16* __restrict__ dlo,
                                                     int K, int N) {
    __shared__ float s[32][33];
    size_t zo = (size_t)blockIdx.z * K * N;
    src += zo; dhi += zo; dlo += zo;
    int n0 = blockIdx.x * 32, k0 = blockIdx.y * 32;
    int tx = threadIdx.x & 31, ty = threadIdx.x >> 5;
#pragma unroll
    for (int i = 0; i < 4; i++)
        s[ty + 8 * i][tx] = src[(size_t)(k0 + ty + 8 * i) * N + n0 + tx];
    __syncthreads();
#pragma unroll
    for (int i = 0; i < 4; i++) {
        int n = n0 + ty + 8 * i, k = k0 + tx;
        float v = s[tx][ty + 8 * i];
        __nv_bfloat16 h, l;
        fsplit(v, h, l);
        dhi[(size_t)n * K + k] = h;
        dlo[(size_t)n * K + k] = l;
    }
}

// ---------------- embedding + positional encoding ----------------
__global__ void embed_kernel(const float* __restrict__ emb,
                             const int* __restrict__ ids,
                             float* __restrict__ x) {
    int idx = blockIdx.x * 256 + threadIdx.x;
    if (idx >= TT * DD) return;
    int t = idx >> 10;
    int d = idx & (DD - 1);
    int pos = t & (SS - 1);
    float val = emb[ids[t] * DD + d] * 32.0f;
    float ang = (float)pos * expf((float)(d & ~1) * (-9.210340371976184f / 1024.0f));
    val += (d & 1) ? cosf(ang) : sinf(ang);
    x[idx] = val;
}

// ---------------- layernorm -> split bf16 output ----------------
__global__ __launch_bounds__(256) void ln_kernel(const float* __restrict__ x,
                                                 const float* __restrict__ g,
                                                 const float* __restrict__ bta,
                                                 __nv_bfloat16* __restrict__ ohi,
                                                 __nv_bfloat16* __restrict__ olo) {
    int row = blockIdx.x;
    const float* xr = x + (size_t)row * DD;
    float s1 = 0.f, s2 = 0.f;
    for (int i = threadIdx.x; i < DD; i += 256) {
        float v = xr[i];
        s1 += v;
        s2 = fmaf(v, v, s2);
    }
    for (int o = 16; o; o >>= 1) {
        s1 += __shfl_xor_sync(0xffffffffu, s1, o);
        s2 += __shfl_xor_sync(0xffffffffu, s2, o);
    }
    __shared__ float r1[8], r2[8];
    __shared__ float smean, srstd;
    int w = threadIdx.x >> 5, lane = threadIdx.x & 31;
    if (lane == 0) { r1[w] = s1; r2[w] = s2; }
    __syncthreads();
    if (threadIdx.x == 0) {
        float t1 = 0.f, t2 = 0.f;
        for (int i = 0; i < 8; i++) { t1 += r1[i]; t2 += r2[i]; }
        float mean = t1 * (1.0f / DD);
        float var  = t2 * (1.0f / DD) - mean * mean;
        smean = mean;
        srstd = rsqrtf(var + 1e-5f);
    }
    __syncthreads();
    float mean = smean, rstd = srstd;
    for (int i = threadIdx.x; i < DD; i += 256) {
        float v = (xr[i] - mean) * rstd * g[i] + bta[i];
        __nv_bfloat16 h, l;
        fsplit(v, h, l);
        ohi[(size_t)row * DD + i] = h;
        olo[(size_t)row * DD + i] = l;
    }
}

// ---------------- bf16x3 mma.sync GEMM with cp.async + ldmatrix ----------------
#define TST 80
#define TILE_B (128 * TST)
#define BUF_B (4 * TILE_B)
#define GEMM_SMEM (2 * BUF_B)

__device__ __forceinline__ void gemm12_body(
    const __nv_bfloat16* __restrict__ Ahg, const __nv_bfloat16* __restrict__ Alg,
    const __nv_bfloat16* __restrict__ Bhg, const __nv_bfloat16* __restrict__ Blg,
    const float* __restrict__ bias, const float* __restrict__ res,
    float* __restrict__ Cf, __nv_bfloat16* __restrict__ Chi, __nv_bfloat16* __restrict__ Clo,
    int N, int K, int act, int bm, int bn, char* smem)
{
    uint32_t sbase = smem_u32(smem);
    int t = threadIdx.x, w = t >> 5, l = t & 31;
    int wm = w >> 2, wn = w & 3;
    int m_base = wm * 64, n_base = wn * 32;

    int lrow = w * 8 + (l & 7);
    int lc = l >> 3;
    const __nv_bfloat16* gsrc[4] = {Ahg, Alg, Bhg, Blg};

    float acc[4][4][4];
#pragma unroll
    for (int mf = 0; mf < 4; mf++)
#pragma unroll
        for (int nf = 0; nf < 4; nf++)
#pragma unroll
            for (int r = 0; r < 4; r++) acc[mf][nf][r] = 0.f;

    int S = K >> 5;

    auto load_stage = [&](int s, int bsel) {
        int k0 = s << 5;
        uint32_t bufb = sbase + bsel * BUF_B;
#pragma unroll
        for (int tile = 0; tile < 4; tile++) {
            const __nv_bfloat16* src = gsrc[tile];
            int r0 = ((tile < 2) ? bm : bn) << 7;
            uint32_t tb = bufb + tile * TILE_B;
#pragma unroll
            for (int i = 0; i < 2; i++) {
                int row = lrow + i * 64;
                const void* gp = src + (size_t)(r0 + row) * K + k0 + lc * 8;
                uint32_t dp = tb + row * TST + lc * 16;
                CP_ASYNC16(dp, gp);
            }
        }
    };

    load_stage(0, 0);
    CP_COMMIT();

    for (int s = 0; s < S; s++) {
        int b = s & 1;
        CP_WAIT0();
        __syncthreads();
        if (s + 1 < S) { load_stage(s + 1, b ^ 1); CP_COMMIT(); }

        uint32_t bufb = sbase + b * BUF_B;
        uint32_t aHb = bufb, aLb = bufb + TILE_B;
        uint32_t bHb = bufb + 2 * TILE_B, bLb = bufb + 3 * TILE_B;
#pragma unroll
        for (int ks = 0; ks < 2; ks++) {
            int cb = ks * 2;
            uint32_t bh[4][2], bl[4][2];
#pragma unroll
            for (int nfp = 0; nfp < 2; nfp++) {
                int nr = n_base + nfp * 16 + ((l >> 4) << 3) + (l & 7);
                int cc = cb + ((l >> 3) & 1);
                uint32_t addr = (uint32_t)(nr * TST + cc * 16);
                uint32_t r0, r1, r2, r3;
                LDSM4(r0, r1, r2, r3, bHb + addr);
                bh[nfp * 2][0] = r0; bh[nfp * 2][1] = r1;
                bh[nfp * 2 + 1][0] = r2; bh[nfp * 2 + 1][1] = r3;
                LDSM4(r0, r1, r2, r3, bLb + addr);
                bl[nfp * 2][0] = r0; bl[nfp * 2][1] = r1;
                bl[nfp * 2 + 1][0] = r2; bl[nfp * 2 + 1][1] = r3;
            }
#pragma unroll
            for (int mf = 0; mf < 4; mf++) {
                int mr = m_base + mf * 16 + (l & 15);
                int cc = cb + (l >> 4);
                uint32_t addr = (uint32_t)(mr * TST + cc * 16);
                uint32_t ah[4], al[4];
                LDSM4(ah[0], ah[1], ah[2], ah[3], aHb + addr);
                LDSM4(al[0], al[1], al[2], al[3], aLb + addr);
#pragma unroll
                for (int nf = 0; nf < 4; nf++) mma_bf16(acc[mf][nf], ah, bh[nf]);
#pragma unroll
                for (int nf = 0; nf < 4; nf++) mma_bf16(acc[mf][nf], ah, bl[nf]);
#pragma unroll
                for (int nf = 0; nf < 4; nf++) mma_bf16(acc[mf][nf], al, bh[nf]);
            }
        }
    }

    int gid = l >> 2, tig = l & 3;
#pragma unroll
    for (int mf = 0; mf < 4; mf++) {
        int row0 = (bm << 7) + m_base + mf * 16 + gid;
#pragma unroll
        for (int nf = 0; nf < 4; nf++) {
            int col = (bn << 7) + n_base + nf * 8 + tig * 2;
            float bx = 0.f, by = 0.f;
            if (bias) { bx = bias[col]; by = bias[col + 1]; }
#pragma unroll
            for (int half = 0; half < 2; half++) {
                int row = row0 + half * 8;
                float vx = acc[mf][nf][half * 2 + 0] + bx;
                float vy = acc[mf][nf][half * 2 + 1] + by;
                size_t o = (size_t)row * N + col;
                if (Chi) {
                    if (act) {
                        vx = 0.5f * vx * (1.0f + erff(vx * 0.70710678118654752f));
                        vy = 0.5f * vy * (1.0f + erff(vy * 0.70710678118654752f));
                    }
                    uint32_t ph, pl;
                    split_bf16x2(vx, vy, ph, pl);
                    *(uint32_t*)(Chi + o) = ph;
                    *(uint32_t*)(Clo + o) = pl;
                } else {
                    if (res) {
                        float2 rr = *(const float2*)(res + o);
                        vx += rr.x; vy += rr.y;
                    }
                    float2 ov; ov.x = vx; ov.y = vy;
                    *(float2*)(Cf + o) = ov;
                }
            }
        }
    }
}

__global__ __launch_bounds__(256, 2) void gemm12_kernel(
    const __nv_bfloat16* ah, const __nv_bfloat16* al,
    const __nv_bfloat16* bh, const __nv_bfloat16* bl,
    const float* bias, const float* res,
    float* Cf, __nv_bfloat16* Chi, __nv_bfloat16* Clo, int N, int K, int act, int swap) {
    extern __shared__ char smem[];
    int bm = swap ? blockIdx.x : blockIdx.y;
    int bn = swap ? blockIdx.y : blockIdx.x;
    gemm12_body(ah, al, bh, bl, bias, res, Cf, Chi, Clo, N, K, act, bm, bn, smem);
}

__global__ __launch_bounds__(256, 2) void gemm12_qkv_kernel(
    const __nv_bfloat16* ah, const __nv_bfloat16* al,
    const __nv_bfloat16* wqh, const __nv_bfloat16* wql,
    const __nv_bfloat16* wkh, const __nv_bfloat16* wkl,
    const __nv_bfloat16* wvh, const __nv_bfloat16* wvl,
    const float* bq, const float* bk, const float* bv,
    __nv_bfloat16* qh, __nv_bfloat16* ql,
    __nv_bfloat16* kh, __nv_bfloat16* kl,
    __nv_bfloat16* vh, __nv_bfloat16* vl) {
    extern __shared__ char smem[];
    const __nv_bfloat16 *bhp, *blp; const float* bi;
    __nv_bfloat16 *oh, *ol;
    if (blockIdx.z == 0)      { bhp = wqh; blp = wql; bi = bq; oh = qh; ol = ql; }
    else if (blockIdx.z == 1) { bhp = wkh; blp = wkl; bi = bk; oh = kh; ol = kl; }
    else                      { bhp = wvh; blp = wvl; bi = bv; oh = vh; ol = vl; }
    gemm12_body(ah, al, bhp, blp, bi, nullptr, nullptr, oh, ol, DD, DD, 0,
                blockIdx.y, blockIdx.x, smem);
}

// ---------------- tensor-core flash attention (bf16x3) ----------------
// CTA: 64 q rows x (h, b); 128 threads = 4 warps x m16 slice; kt tiles of 64 keys.
// Row = 64 dims x 2B = 128B; stride 144B (=4-bank step, 8-row phases conflict-free).
#define AST 144
#define ATILE (64 * AST)        // 9216 B
#define ATT_SMEM (6 * ATILE)    // Qh,Ql,Kh,Kl,Vh,Vl = 55296

__global__ __launch_bounds__(128) void flash_attn_kernel(
    const __nv_bfloat16* __restrict__ qhi, const __nv_bfloat16* __restrict__ qlo,
    const __nv_bfloat16* __restrict__ khi, const __nv_bfloat16* __restrict__ klo,
    const __nv_bfloat16* __restrict__ vhi, const __nv_bfloat16* __restrict__ vlo,
    __nv_bfloat16* __restrict__ Ohi, __nv_bfloat16* __restrict__ Olo)
{
    extern __shared__ char sm[];
    uint32_t sb = smem_u32(sm);
    uint32_t Qh = sb, Ql = sb + ATILE, Kh = sb + 2 * ATILE, Kl = sb + 3 * ATILE;
    uint32_t Vh = sb + 4 * ATILE, Vl = sb + 5 * ATILE;

    int t = threadIdx.x, wid = t >> 5, l = t & 31;
    int gid = l >> 2, tig = l & 3;
    int bqx = blockIdx.x, h = blockIdx.y, b = blockIdx.z;
    int q0 = bqx * 64;
    int m_base = wid * 16;
    size_t tok0 = (size_t)(b * SS) * DD + h * 64;   // +token*DD to index

    // ---- load Q tile (hi/lo) ----
    {
        int chunk = t & 7, row0 = t >> 3;           // 16 rows per pass
#pragma unroll
        for (int i = 0; i < 4; i++) {
            int row = row0 + 16 * i;
            size_t g = tok0 + (size_t)(q0 + row) * DD + chunk * 8;
            CP_ASYNC16(Qh + row * AST + chunk * 16, qhi + g);
            CP_ASYNC16(Ql + row * AST + chunk * 16, qlo + g);
        }
    }
    CP_COMMIT();

    float o[8][4];
#pragma unroll
    for (int nf = 0; nf < 8; nf++)
#pragma unroll
        for (int r = 0; r < 4; r++) o[nf][r] = 0.f;
    float m0 = -1e30f, m1 = -1e30f, l0 = 0.f, l1 = 0.f;

    int ntiles = bqx + 1;
    for (int kt = 0; kt < ntiles; kt++) {
        // ---- load K/V tile (hi/lo) ----
        {
            int chunk = t & 7, row0 = t >> 3;
#pragma unroll
            for (int i = 0; i < 4; i++) {
                int row = row0 + 16 * i;
                size_t g = tok0 + (size_t)(kt * 64 + row) * DD + chunk * 8;
                CP_ASYNC16(Kh + row * AST + chunk * 16, khi + g);
                CP_ASYNC16(Kl + row * AST + chunk * 16, klo + g);
                CP_ASYNC16(Vh + row * AST + chunk * 16, vhi + g);
                CP_ASYNC16(Vl + row * AST + chunk * 16, vlo + g);
            }
        }
        CP_COMMIT();
        CP_WAIT0();
        __syncthreads();

        // ---- S = Q K^T (3-pass bf16x3) ----
        float sacc[8][4];
#pragma unroll
        for (int nf = 0; nf < 8; nf++)
#pragma unroll
            for (int r = 0; r < 4; r++) sacc[nf][r] = 0.f;
#pragma unroll
        for (int kb = 0; kb < 4; kb++) {
            uint32_t aoff = (uint32_t)((m_base + (l & 15)) * AST + (kb * 2 + (l >> 4)) * 16);
            uint32_t qh4[4], ql4[4];
            LDSM4(qh4[0], qh4[1], qh4[2], qh4[3], Qh + aoff);
            LDSM4(ql4[0], ql4[1], ql4[2], ql4[3], Ql + aoff);
#pragma unroll
            for (int ng = 0; ng < 4; ng++) {
                uint32_t boff = (uint32_t)((ng * 16 + ((l >> 4) << 3) + (l & 7)) * AST
                                           + (kb * 2 + ((l >> 3) & 1)) * 16);
                uint32_t kh4[4], kl4[4];
                LDSM4(kh4[0], kh4[1], kh4[2], kh4[3], Kh + boff);
                LDSM4(kl4[0], kl4[1], kl4[2], kl4[3], Kl + boff);
                mma_bf16(sacc[2 * ng],     qh4, kh4);
                mma_bf16(sacc[2 * ng + 1], qh4, kh4 + 2);
                mma_bf16(sacc[2 * ng],     qh4, kl4);
                mma_bf16(sacc[2 * ng + 1], qh4, kl4 + 2);
                mma_bf16(sacc[2 * ng],     ql4, kh4);
                mma_bf16(sacc[2 * ng + 1], ql4, kh4 + 2);
            }
        }

        // ---- scale + causal mask ----
#pragma unroll
        for (int nf = 0; nf < 8; nf++)
#pragma unroll
            for (int r = 0; r < 4; r++) sacc[nf][r] *= 0.125f;
        if (kt == bqx) {
            int grow0 = q0 + m_base + gid, grow1 = grow0 + 8;
#pragma unroll
            for (int nf = 0; nf < 8; nf++) {
                int gc = kt * 64 + nf * 8 + tig * 2;
                if (gc > grow0)     sacc[nf][0] = -1e30f;
                if (gc + 1 > grow0) sacc[nf][1] = -1e30f;
                if (gc > grow1)     sacc[nf][2] = -1e30f;
                if (gc + 1 > grow1) sacc[nf][3] = -1e30f;
            }
        }

        // ---- online softmax (registers + shfl over 4 lanes/row) ----
        float mx0 = -1e30f, mx1 = -1e30f;
#pragma unroll
        for (int nf = 0; nf < 8; nf++) {
            mx0 = fmaxf(mx0, fmaxf(sacc[nf][0], sacc[nf][1]));
            mx1 = fmaxf(mx1, fmaxf(sacc[nf][2], sacc[nf][3]));
        }
        mx0 = fmaxf(mx0, __shfl_xor_sync(0xffffffffu, mx0, 1));
        mx0 = fmaxf(mx0, __shfl_xor_sync(0xffffffffu, mx0, 2));
        mx1 = fmaxf(mx1, __shfl_xor_sync(0xffffffffu, mx1, 1));
        mx1 = fmaxf(mx1, __shfl_xor_sync(0xffffffffu, mx1, 2));
        float mn0 = fmaxf(m0, mx0), mn1 = fmaxf(m1, mx1);
        float f0 = __expf(m0 - mn0), f1 = __expf(m1 - mn1);
        float s0 = 0.f, s1 = 0.f;
#pragma unroll
        for (int nf = 0; nf < 8; nf++) {
            float p0 = __expf(sacc[nf][0] - mn0);
            float p1 = __expf(sacc[nf][1] - mn0);
            float p2 = __expf(sacc[nf][2] - mn1);
            float p3 = __expf(sacc[nf][3] - mn1);
            sacc[nf][0] = p0; sacc[nf][1] = p1; sacc[nf][2] = p2; sacc[nf][3] = p3;
            s0 += p0 + p1; s1 += p2 + p3;
        }
        s0 += __shfl_xor_sync(0xffffffffu, s0, 1);
        s0 += __shfl_xor_sync(0xffffffffu, s0, 2);
        s1 += __shfl_xor_sync(0xffffffffu, s1, 1);
        s1 += __shfl_xor_sync(0xffffffffu, s1, 2);
        l0 = l0 * f0 + s0; l1 = l1 * f1 + s1;
        m0 = mn0; m1 = mn1;
#pragma unroll
        for (int nf = 0; nf < 8; nf++) {
            o[nf][0] *= f0; o[nf][1] *= f0; o[nf][2] *= f1; o[nf][3] *= f1;
        }

        // ---- P -> A fragments (C(m16n16) == A(m16k16) identity), split hi/lo ----
        uint32_t phi[4][4], plo[4][4];
#pragma unroll
        for (int kb = 0; kb < 4; kb++) {
            split_bf16x2(sacc[2 * kb][0],     sacc[2 * kb][1],     phi[kb][0], plo[kb][0]);
            split_bf16x2(sacc[2 * kb][2],     sacc[2 * kb][3],     phi[kb][1], plo[kb][1]);
            split_bf16x2(sacc[2 * kb + 1][0], sacc[2 * kb + 1][1], phi[kb][2], plo[kb][2]);
            split_bf16x2(sacc[2 * kb + 1][2], sacc[2 * kb + 1][3], phi[kb][3], plo[kb][3]);
        }

        // ---- O += P V (V via ldmatrix.trans, 3-pass) ----
#pragma unroll
        for (int kb = 0; kb < 4; kb++) {
#pragma unroll
            for (int dg = 0; dg < 4; dg++) {
                uint32_t voff = (uint32_t)((kb * 16 + ((l >> 3) & 1) * 8 + (l & 7)) * AST
                                           + dg * 32 + (l >> 4) * 16);
                uint32_t vh4[4], vl4[4];
                LDSM4T(vh4[0], vh4[1], vh4[2], vh4[3], Vh + voff);
                LDSM4T(vl4[0], vl4[1], vl4[2], vl4[3], Vl + voff);
                mma_bf16(o[2 * dg],     phi[kb], vh4);
                mma_bf16(o[2 * dg + 1], phi[kb], vh4 + 2);
                mma_bf16(o[2 * dg],     phi[kb], vl4);
                mma_bf16(o[2 * dg + 1], phi[kb], vl4 + 2);
                mma_bf16(o[2 * dg],     plo[kb], vh4);
                mma_bf16(o[2 * dg + 1], plo[kb], vh4 + 2);
            }
        }
        __syncthreads();
    }

    // ---- normalize + split-store ----
    float inv0 = 1.0f / l0, inv1 = 1.0f / l1;
    int row0 = b * SS + q0 + m_base + gid;
#pragma unroll
    for (int nf = 0; nf < 8; nf++) {
        int col = h * 64 + nf * 8 + tig * 2;
        uint32_t ph, pl;
        split_bf16x2(o[nf][0] * inv0, o[nf][1] * inv0, ph, pl);
        size_t oa = (size_t)row0 * DD + col;
        *(uint32_t*)(Ohi + oa) = ph;
        *(uint32_t*)(Olo + oa) = pl;
        split_bf16x2(o[nf][2] * inv1, o[nf][3] * inv1, ph, pl);
        size_t ob = (size_t)(row0 + 8) * DD + col;
        *(uint32_t*)(Ohi + ob) = ph;
        *(uint32_t*)(Olo + ob) = pl;
    }
}

// ---------------- launch ----------------
extern "C" void kernel_launch(void* const* d_in, const int* in_sizes, int n_in,
                              void* d_out, int out_size) {
    const float* emb  = (const float*)d_in[0];
    const float* Wq   = (const float*)d_in[1];
    const float* bq   = (const float*)d_in[2];
    const float* Wk   = (const float*)d_in[3];
    const float* bk   = (const float*)d_in[4];
    const float* Wv   = (const float*)d_in[5];
    const float* bv   = (const float*)d_in[6];
    const float* Wo   = (const float*)d_in[7];
    const float* bo   = (const float*)d_in[8];
    const float* ln1g = (const float*)d_in[9];
    const float* ln1b = (const float*)d_in[10];
    const float* W1   = (const float*)d_in[11];
    const float* b1   = (const float*)d_in[12];
    const float* W2   = (const float*)d_in[13];
    const float* b2   = (const float*)d_in[14];
    const float* ln2g = (const float*)d_in[15];
    const float* ln2b = (const float*)d_in[16];
    const float* lnfg = (const float*)d_in[17];
    const float* lnfb = (const float*)d_in[18];
    const float* Wout = (const float*)d_in[19];
    const int*   ids  = (const int*)d_in[20];

    __nv_bfloat16 *whi, *wlo, *hhi, *hlo, *athi, *atlo, *ffhi, *fflo;
    __nv_bfloat16 *qhi, *qlo, *khi, *klo, *vhi, *vlo;
    float *x;
    cudaGetSymbolAddress((void**)&whi, g_whi);
    cudaGetSymbolAddress((void**)&wlo, g_wlo);
    cudaGetSymbolAddress((void**)&x,   g_x);
    cudaGetSymbolAddress((void**)&qhi, g_qhi);
    cudaGetSymbolAddress((void**)&qlo, g_qlo);
    cudaGetSymbolAddress((void**)&khi, g_khi);
    cudaGetSymbolAddress((void**)&klo, g_klo);
    cudaGetSymbolAddress((void**)&vhi, g_vhi);
    cudaGetSymbolAddress((void**)&vlo, g_vlo);
    cudaGetSymbolAddress((void**)&hhi, g_hhi);
    cudaGetSymbolAddress((void**)&hlo, g_hlo);
    cudaGetSymbolAddress((void**)&athi, g_athi);
    cudaGetSymbolAddress((void**)&atlo, g_atlo);
    cudaGetSymbolAddress((void**)&ffhi, g_ffhi);
    cudaGetSymbolAddress((void**)&fflo, g_fflo);

    static int attr_set = 0;
    if (!attr_set) {
        cudaFuncSetAttribute(flash_attn_kernel, cudaFuncAttributeMaxDynamicSharedMemorySize, ATT_SMEM);
        cudaFuncSetAttribute(gemm12_kernel, cudaFuncAttributeMaxDynamicSharedMemorySize, GEMM_SMEM);
        cudaFuncSetAttribute(gemm12_qkv_kernel, cudaFuncAttributeMaxDynamicSharedMemorySize, GEMM_SMEM);
        attr_set = 1;
    }

    // ---- weight prep: transpose + split ----
    tsplit_kernel<<<dim3(DD / 32, DD / 32, LL), 256>>>(Wq, whi + OFF_WQ, wlo + OFF_WQ, DD, DD);
    tsplit_kernel<<<dim3(DD / 32, DD / 32, LL), 256>>>(Wk, whi + OFF_WK, wlo + OFF_WK, DD, DD);
    tsplit_kernel<<<dim3(DD / 32, DD / 32, LL), 256>>>(Wv, whi + OFF_WV, wlo + OFF_WV, DD, DD);
    tsplit_kernel<<<dim3(DD / 32, DD / 32, LL), 256>>>(Wo, whi + OFF_WO, wlo + OFF_WO, DD, DD);
    tsplit_kernel<<<dim3(FFD / 32, DD / 32, LL), 256>>>(W1, whi + OFF_W1, wlo + OFF_W1, DD, FFD);
    tsplit_kernel<<<dim3(DD / 32, FFD / 32, LL), 256>>>(W2, whi + OFF_W2, wlo + OFF_W2, FFD, DD);
    tsplit_kernel<<<dim3(VV / 32, DD / 32, 1), 256>>>(Wout, whi + OFF_WOUT, wlo + OFF_WOUT, DD, VV);

    embed_kernel<<<(TT * DD) / 256, 256>>>(emb, ids, x);

    dim3 gN1(DD / 128, TT / 128);        // (8, 16)
    dim3 gQKV(DD / 128, TT / 128, 3);    // (8, 16, 3)
    dim3 gFF1(FFD / 128, TT / 128);      // (32, 16)
    dim3 gOut(TT / 128, VV / 128);       // (16, 250)
    dim3 gAttn(SS / 64, HH, BB);         // (16, 16, 2)

    for (int l = 0; l < LL; l++) {
        size_t wo1 = (size_t)l * DD * DD;
        size_t woF = (size_t)l * DD * FFD;
        ln_kernel<<<TT, 256>>>(x, ln1g + l * DD, ln1b + l * DD, hhi, hlo);
        gemm12_qkv_kernel<<<gQKV, 256, GEMM_SMEM>>>(
            hhi, hlo,
            whi + OFF_WQ + wo1, wlo + OFF_WQ + wo1,
            whi + OFF_WK + wo1, wlo + OFF_WK + wo1,
            whi + OFF_WV + wo1, wlo + OFF_WV + wo1,
            bq + l * DD, bk + l * DD, bv + l * DD,
            qhi, qlo, khi, klo, vhi, vlo);
        flash_attn_kernel<<<gAttn, 128, ATT_SMEM>>>(qhi, qlo, khi, klo, vhi, vlo, athi, atlo);
        gemm12_kernel<<<gN1, 256, GEMM_SMEM>>>(
            athi, atlo, whi + OFF_WO + wo1, wlo + OFF_WO + wo1,
            bo + l * DD, x, x, nullptr, nullptr, DD, DD, 0, 0);
        ln_kernel<<<TT, 256>>>(x, ln2g + l * DD, ln2b + l * DD, hhi, hlo);
        gemm12_kernel<<<gFF1, 256, GEMM_SMEM>>>(
            hhi, hlo, whi + OFF_W1 + woF, wlo + OFF_W1 + woF,
            b1 + l * FFD, nullptr, nullptr, ffhi, fflo, FFD, DD, 1, 0);
        gemm12_kernel<<<gN1, 256, GEMM_SMEM>>>(
            ffhi, fflo, whi + OFF_W2 + woF, wlo + OFF_W2 + woF,
            b2 + l * DD, x, x, nullptr, nullptr, DD, FFD, 0, 0);
    }
    ln_kernel<<<TT, 256>>>(x, lnfg, lnfb, hhi, hlo);
    gemm12_kernel<<<gOut, 256, GEMM_SMEM>>>(
        hhi, hlo, whi + OFF_WOUT, wlo + OFF_WOUT,
        nullptr, nullptr, (float*)d_out, nullptr, nullptr, VV, DD, 0, 1);
}